// round 13
// baseline (speedup 1.0000x reference)
#include <cuda_runtime.h>
#include <cstdint>

// Problem constants (256x256 grid, 4-adjacency)
#define L_    65536      // leaves
#define NN    131071     // 2L-1 nodes
#define NPAD  262144     // 2^18 >= 130560 edges
#define MACC  (L_ - 1)   // accepted merges = 65535
#define FULLM 0xFFFFFFFFu
#define ELEN  (2 * NN)   // Euler elements = 262142
#define ESENT ELEN       // sentinel element
#define EP    262144     // Euler plane stride (pow2 >= ELEN)
#define CHUNK 1024       // fine chunk (phase2 granularity)
#define CHUNK1 8192      // coarse chunk (phase1a granularity)
#define NC1   16         // coarse chunks
#define NCMAX 256
#define EVN   131072     // 2^17 >= 2*MACC event keys
#define NB    8192       // sort buckets
#define BCAP  64         // bucket capacity (Poisson(16); P(>64) ~ e^-40)

// ---------------- device scratch ----------------
__device__ unsigned long long g_keys2[NB * BCAP];  // padded bucket slots (4MB)
__device__ unsigned int   g_bcnt[NB];
__device__ unsigned int   g_boffs[NB];
__device__ unsigned long long g_esort[NPAD];  // (wbits<<32)|(v<<16)|u in rank order
__device__ unsigned int   g_lab[NPAD];        // labels: coarse then refined (a|b<<16)
__device__ unsigned int   g_recTmp[NPAD];     // per-chunk records
__device__ unsigned int   g_srcTmp[NPAD];     // per-chunk source edge index
__device__ unsigned int   g_acnt[NCMAX];
__device__ unsigned int   g_abase[NCMAX];
__device__ unsigned int g_rec[MACC];          // accepted i -> (win_min<<16)|lose_min
__device__ unsigned int g_ev2[EVN];           // event keys (v<<16)|k, then sorted
__device__ unsigned int g_parent[NN];
__device__ float        g_alt[NN];
__device__ unsigned int g_chw[MACC];          // child node on win-min side
__device__ unsigned int g_chl[MACC];          // child node on lose-min side
__device__ unsigned long long g_nd[2][ELEN + 1];  // Euler (nx | dd<<32), ping-pong
__device__ unsigned int g_pos[ELEN];          // Euler position
__device__ float        g_ev[20 * EP];        // planes 0..9 leaf moments, 10..19 path sums
__device__ float        g_part[20 * 256];     // scan block partials
__device__ float        g_ins[NN];            // inside(a) for internal nodes

// ---------------- init (fused zeroing) ----------------
__global__ void k_init(int M) {
    int i = blockIdx.x * blockDim.x + threadIdx.x;   // 262144 threads
    if (i < NN) { g_parent[i] = i; g_alt[i] = 0.0f; }
    if (i < NB) g_bcnt[i] = 0u;
    if (i >= 2 * MACC && i < EVN) g_ev2[i] = FULLM;
    #pragma unroll
    for (int p = 0; p < 10; p++) g_ev[p * EP + i] = 0.0f;   // planes 0..9 fully
    if (i >= ELEN) {                                        // planes 10..19: tail only
        #pragma unroll
        for (int p = 10; p < 20; p++) g_ev[p * EP + i] = 0.0f;
    }
}

// ---------------- bucket sort of (weight, idx) keys ----------------
__global__ void k_bscatter(const float* __restrict__ ew, int M) {
    int e = blockIdx.x * blockDim.x + threadIdx.x;
    if (e >= M) return;
    float w = ew[e];
    unsigned int b = min((unsigned int)(w * (float)NB), (unsigned int)(NB - 1));
    unsigned int slot = atomicAdd(&g_bcnt[b], 1u);
    if (slot < BCAP)
        g_keys2[b * BCAP + slot] = ((unsigned long long)__float_as_uint(w) << 32) | (unsigned int)e;
}

__global__ void k_bscan() {
    __shared__ unsigned int s[1024];
    __shared__ unsigned int s_run;
    int t = threadIdx.x;
    if (t == 0) s_run = 0u;
    __syncthreads();
    for (int c = 0; c < NB / 1024; c++) {
        unsigned int x = g_bcnt[c * 1024 + t];
        s[t] = x;
        __syncthreads();
        for (int off = 1; off < 1024; off <<= 1) {
            unsigned int y = (t >= off) ? s[t - off] : 0u;
            __syncthreads();
            s[t] += y;
            __syncthreads();
        }
        unsigned int run = s_run;
        g_boffs[c * 1024 + t] = run + s[t] - x;   // exclusive
        unsigned int tot = s[1023];
        __syncthreads();
        if (t == 0) s_run = run + tot;
        __syncthreads();
    }
}

// warp-per-bucket 64-wide bitonic (unique keys => stability); compacts + gathers endpoints
__global__ void __launch_bounds__(256) k_bsort(const int* __restrict__ src,
                                               const int* __restrict__ dst) {
    __shared__ unsigned long long s[8][BCAP];
    int wid  = threadIdx.x >> 5;
    int lane = threadIdx.x & 31;
    int b = blockIdx.x * 8 + wid;
    unsigned int cnt  = min(g_bcnt[b], (unsigned int)BCAP);
    unsigned int offs = g_boffs[b];
    s[wid][lane]      = (lane < (int)cnt)      ? g_keys2[b * BCAP + lane]      : ~0ull;
    s[wid][lane + 32] = (lane + 32 < (int)cnt) ? g_keys2[b * BCAP + lane + 32] : ~0ull;
    __syncwarp();
    #pragma unroll
    for (int k = 2; k <= BCAP; k <<= 1) {
        for (int j = k >> 1; j > 0; j >>= 1) {
            int pos = ((lane & ~(j - 1)) << 1) | (lane & (j - 1));
            bool asc = ((pos & k) == 0);
            unsigned long long x = s[wid][pos], y = s[wid][pos + j];
            if ((x > y) == asc) { s[wid][pos] = y; s[wid][pos + j] = x; }
            __syncwarp();
        }
    }
    for (int i = lane; i < (int)cnt; i += 32) {
        unsigned long long key = s[wid][i];
        unsigned int idx = (unsigned int)(key & 0xFFFFFFFFull);
        unsigned int wb  = (unsigned int)(key >> 32);
        unsigned int u = (unsigned int)src[idx];
        unsigned int v = (unsigned int)dst[idx];
        g_esort[offs + i] = ((unsigned long long)wb << 32) | (v << 16) | u;
    }
}

// ---------------- union-find helpers (smem, root = component min) ----------------
__device__ __forceinline__ unsigned int sfind(volatile unsigned short* uf, unsigned int x) {
    unsigned int p;
    while ((p = uf[x]) != x) {
        unsigned int gp = uf[p];
        if (gp != p) uf[x] = (unsigned short)gp;   // path halving (benign races)
        x = p;
    }
    return x;
}

__device__ __forceinline__ void shook(unsigned short* uf, unsigned int u, unsigned int v) {
    for (;;) {
        unsigned int a = sfind(uf, u), b = sfind(uf, v);
        if (a == b) break;
        unsigned int hi = a > b ? a : b;
        unsigned int lo = a ^ b ^ hi;
        if (atomicCAS(&uf[hi], (unsigned short)hi, (unsigned short)lo) == (unsigned short)hi)
            break;
    }
}

// ---------------- phase 1a: COARSE labels (16 sequential rounds, one block) ----------
__global__ void __launch_bounds__(1024) k_phase1a(int M) {
    extern __shared__ unsigned short s_uf[];   // 65536 x u16 = 128KB
    int t = threadIdx.x;
    unsigned int* uf32 = (unsigned int*)s_uf;
    for (int i = t; i < L_ / 2; i += 1024)
        uf32[i] = (2u * i) | ((2u * i + 1u) << 16);
    __syncthreads();
    for (int c = 0; c < NC1; c++) {
        int base = c * CHUNK1;
        int n = min(CHUNK1, M - base);
        if (n <= 0) break;
        for (int e = t; e < n; e += 1024) {
            unsigned long long cur = g_esort[base + e];
            unsigned int u = (unsigned int)cur & 0xFFFFu;
            unsigned int v = ((unsigned int)cur >> 16) & 0xFFFFu;
            unsigned int a = sfind(s_uf, u);
            unsigned int b = sfind(s_uf, v);
            g_lab[base + e] = a | (b << 16);          // coarse labels
        }
        __syncthreads();
        for (int e = t; e < n; e += 1024) {
            unsigned long long cur = g_esort[base + e];
            shook(s_uf, (unsigned int)cur & 0xFFFFu, ((unsigned int)cur >> 16) & 0xFFFFu);
        }
        __syncthreads();
    }
}

// ---------------- phase 1b: refine to 1024-granularity (16 concurrent blocks) --------
// Block C: private UF seeded identity; coarse labels are prefix-before-C component mins,
// so find(coarse(u)) after hooking sub-chunks 0..s-1 = prefix-before-sub-chunk-s min.
__global__ void __launch_bounds__(1024) k_phase1b(int M) {
    extern __shared__ unsigned short s_uf[];
    int c = blockIdx.x;
    int t = threadIdx.x;
    unsigned int* uf32 = (unsigned int*)s_uf;
    for (int i = t; i < L_ / 2; i += 1024)
        uf32[i] = (2u * i) | ((2u * i + 1u) << 16);
    __syncthreads();
    for (int s = 0; s < CHUNK1 / CHUNK; s++) {
        int base = c * CHUNK1 + s * CHUNK;
        int n = min(CHUNK, M - base);
        if (n <= 0) break;
        unsigned int cu = 0, cv = 0;
        bool has = (t < n);
        if (has) {
            unsigned int coarse = g_lab[base + t];    // coarse labels from phase1a
            cu = coarse & 0xFFFFu;
            cv = coarse >> 16;
            unsigned int a = sfind(s_uf, cu);
            unsigned int b = sfind(s_uf, cv);
            g_lab[base + t] = a | (b << 16);          // refined labels
        }
        __syncthreads();
        if (has) shook(s_uf, cu, cv);
        __syncthreads();
    }
}

// ---------------- phase 2: independent serial replay per fine chunk ----------------
__device__ __forceinline__ unsigned int uf_find(volatile unsigned short* uf, unsigned int x) {
    unsigned int r = x, p;
    while ((p = uf[r]) != r) r = p;
    while ((p = uf[x]) != r) { uf[x] = (unsigned short)r; x = p; }
    return r;
}

__global__ void __launch_bounds__(1024) k_phase2(int M) {
    extern __shared__ unsigned short s_uf[];
    int c = blockIdx.x;
    int base = c * CHUNK;
    int n = min(CHUNK, M - base);
    unsigned int* uf32 = (unsigned int*)s_uf;
    for (int i = threadIdx.x; i < L_ / 2; i += blockDim.x)
        uf32[i] = (2u * i) | ((2u * i + 1u) << 16);
    __syncthreads();
    if (threadIdx.x == 0) {
        unsigned int cnt = 0;
        for (int e = 0; e < n; e++) {
            unsigned int lab = g_lab[base + e];
            unsigned int a = uf_find(s_uf, lab & 0xFFFFu);
            unsigned int b = uf_find(s_uf, lab >> 16);
            if (a == b) continue;
            unsigned int w = a < b ? a : b;
            unsigned int l = a ^ b ^ w;
            s_uf[l] = (unsigned short)w;
            g_recTmp[base + cnt] = (w << 16) | l;
            g_srcTmp[base + cnt] = (unsigned int)(base + e);
            cnt++;
        }
        g_acnt[c] = cnt;
    }
}

__global__ void k_ascan(int nc) {
    __shared__ unsigned int s[NCMAX];
    int t = threadIdx.x;
    unsigned int x = (t < nc) ? g_acnt[t] : 0u;
    s[t] = x;
    __syncthreads();
    for (int off = 1; off < NCMAX; off <<= 1) {
        unsigned int y = (t >= off) ? s[t - off] : 0u;
        __syncthreads();
        s[t] += y;
        __syncthreads();
    }
    if (t < nc) g_abase[t] = s[t] - x;   // exclusive
}

__global__ void k_ascatter(int nc) {
    int i = blockIdx.x * blockDim.x + threadIdx.x;
    int c = i / CHUNK, li = i % CHUNK;
    if (c >= nc || (unsigned int)li >= g_acnt[c]) return;
    unsigned int slot = g_abase[c] + (unsigned int)li;
    unsigned int rec = g_recTmp[c * CHUNK + li];
    g_rec[slot] = rec;
    unsigned int e = g_srcTmp[c * CHUNK + li];
    g_alt[L_ + slot] = __uint_as_float((unsigned int)(g_esort[e] >> 32));
    g_ev2[2 * slot]     = ((rec >> 16) << 16) | slot;       // win event
    g_ev2[2 * slot + 1] = ((rec & 0xFFFFu) << 16) | slot;   // lose event
}

// ---------------- bitonic sort, 32-bit event keys (8192-wide tiles) ----------------
__global__ void __launch_bounds__(1024) k_esort_local_init() {
    __shared__ unsigned int s[8192];
    int base = blockIdx.x * 8192;
    int t = threadIdx.x;
    #pragma unroll
    for (int i = 0; i < 8; i++) s[t + i * 1024] = g_ev2[base + t + i * 1024];
    __syncthreads();
    for (int k = 2; k <= 8192; k <<= 1) {
        for (int j = k >> 1; j > 0; j >>= 1) {
            #pragma unroll
            for (int q = 0; q < 4; q++) {
                int p = t + q * 1024;
                int pos = ((p & ~(j - 1)) << 1) | (p & (j - 1));
                bool asc = (((base + pos) & k) == 0);
                unsigned int x = s[pos], y = s[pos + j];
                if ((x > y) == asc) { s[pos] = y; s[pos + j] = x; }
            }
            __syncthreads();
        }
    }
    #pragma unroll
    for (int i = 0; i < 8; i++) g_ev2[base + t + i * 1024] = s[t + i * 1024];
}

__global__ void k_esort_global(int j, int k) {
    int t = blockIdx.x * blockDim.x + threadIdx.x;
    int i = ((t & ~(j - 1)) << 1) | (t & (j - 1));
    int l = i + j;
    bool asc = ((i & k) == 0);
    unsigned int x = g_ev2[i], y = g_ev2[l];
    if ((x > y) == asc) { g_ev2[i] = y; g_ev2[l] = x; }
}

__global__ void __launch_bounds__(1024) k_esort_local_tail(int k) {
    __shared__ unsigned int s[8192];
    int base = blockIdx.x * 8192;
    int t = threadIdx.x;
    #pragma unroll
    for (int i = 0; i < 8; i++) s[t + i * 1024] = g_ev2[base + t + i * 1024];
    __syncthreads();
    bool asc = ((base & k) == 0);   // k >= 16384 > tile: constant per tile
    for (int j = 4096; j > 0; j >>= 1) {
        #pragma unroll
        for (int q = 0; q < 4; q++) {
            int p = t + q * 1024;
            int pos = ((p & ~(j - 1)) << 1) | (p & (j - 1));
            unsigned int x = s[pos], y = s[pos + j];
            if ((x > y) == asc) { s[pos] = y; s[pos + j] = x; }
        }
        __syncthreads();
    }
    #pragma unroll
    for (int i = 0; i < 8; i++) g_ev2[base + t + i * 1024] = s[t + i * 1024];
}

// parallel chain links from sorted events
__global__ void k_vlink2() {
    int i = blockIdx.x * blockDim.x + threadIdx.x;
    if (i >= 2 * MACC) return;
    unsigned int key = g_ev2[i];
    unsigned int v = key >> 16, k = key & 0xFFFFu;
    unsigned int prevnode;
    if (i == 0 || (g_ev2[i - 1] >> 16) != v)
        prevnode = v;
    else
        prevnode = L_ + (g_ev2[i - 1] & 0xFFFFu);
    g_parent[prevnode] = L_ + k;
    if ((g_rec[k] >> 16) == v) g_chw[k] = prevnode;
    else                       g_chl[k] = prevnode;
}

// ---------------- Euler tour + list ranking (quad-hop doubling) ----------------
__global__ void k_euler() {
    int n = blockIdx.x * blockDim.x + threadIdx.x;
    if (n >= NN) return;
    if (n == 0) g_nd[0][ESENT] = (unsigned long long)ESENT;   // dd=0 self-loop
    const unsigned long long ONE = 1ull << 32;
    if (n < L_) {
        g_nd[0][n] = (unsigned long long)(NN + n) | ONE;
    } else {
        int k = n - L_;
        unsigned int cw = g_chw[k], cl = g_chl[k];
        g_nd[0][n]       = (unsigned long long)cw | ONE;
        g_nd[0][NN + cw] = (unsigned long long)cl | ONE;
        g_nd[0][NN + cl] = (unsigned long long)(NN + n) | ONE;
    }
    if (n == NN - 1) g_nd[0][NN + n] = (unsigned long long)ESENT | ONE;
}

// quad-hop: one launch = two doubling rounds (4 hops). 4^9 = 2^18 >= ELEN.
__global__ void k_rank4(int s) {
    int e = blockIdx.x * blockDim.x + threadIdx.x;
    if (e > ELEN) return;
    unsigned long long a = g_nd[s][e];
    unsigned long long b = g_nd[s][(unsigned int)a];
    unsigned long long c = g_nd[s][(unsigned int)b];
    unsigned long long d = g_nd[s][(unsigned int)c];
    unsigned long long dd = (a >> 32) + (b >> 32) + (c >> 32) + (d >> 32);
    g_nd[1 - s][e] = (unsigned long long)(unsigned int)d | (dd << 32);
}

// final: positions; fuse leaf moment scatter (element id < L_ = down(leaf))
__global__ void k_rank_fin(int s) {
    int e = blockIdx.x * blockDim.x + threadIdx.x;
    if (e >= ELEN) return;
    unsigned long long x = g_nd[s][e];
    unsigned long long y = g_nd[s][(unsigned int)x];
    unsigned int dd = (unsigned int)((x >> 32) + (y >> 32));
    unsigned int p = (unsigned int)ELEN - dd;
    g_pos[e] = p;
    if (e < L_) {   // down(leaf e): scatter moments of alt(parent(leaf))
        float yv = g_alt[g_parent[e]];
        float pw = 1.0f;
        #pragma unroll
        for (int i = 0; i < 10; i++) { g_ev[i * EP + p] = pw; pw *= yv; }
    }
}

// planes 10..19: +val at down(n), -val at up(n); sz from Euler positions:
// leaves(n) = (pos_up - pos_down + 3) >> 2  (full binary tree)
__global__ void k_pscatter() {
    int n = blockIdx.x * blockDim.x + threadIdx.x;
    if (n >= NN) return;
    unsigned int pd = g_pos[n], pu = g_pos[NN + n];
    float sz = (float)((pu - pd + 3u) >> 2);
    float x  = g_alt[n];
    unsigned int p = g_parent[n];
    bool isroot = (p == (unsigned int)n);
    float y = g_alt[p];
    float xp = 1.0f, yp = 1.0f;
    #pragma unroll
    for (int i = 0; i < 10; i++) {
        float val = sz * (xp - (isroot ? 0.0f : yp));
        g_ev[(10 + i) * EP + pd] = val;
        g_ev[(10 + i) * EP + pu] = -val;
        xp *= x; yp *= y;
    }
}

// ---------------- 3-phase inclusive prefix scan (all 20 planes in one round) ----------
__global__ void k_scan1() {
    __shared__ float s[1024];
    int plane = blockIdx.y;
    int gi = blockIdx.x * 1024 + threadIdx.x;
    int t = threadIdx.x;
    float x = g_ev[plane * EP + gi];
    s[t] = x;
    __syncthreads();
    for (int off = 1; off < 1024; off <<= 1) {
        float y = (t >= off) ? s[t - off] : 0.0f;
        __syncthreads();
        s[t] += y;
        __syncthreads();
    }
    g_ev[plane * EP + gi] = s[t];
    if (t == 1023) g_part[plane * 256 + blockIdx.x] = s[1023];
}

__global__ void k_scan2() {
    __shared__ float s[256];
    int plane = blockIdx.y;
    int t = threadIdx.x;
    float x = g_part[plane * 256 + t];
    s[t] = x;
    __syncthreads();
    for (int off = 1; off < 256; off <<= 1) {
        float y = (t >= off) ? s[t - off] : 0.0f;
        __syncthreads();
        s[t] += y;
        __syncthreads();
    }
    g_part[plane * 256 + t] = s[t] - x;   // exclusive
}

__global__ void k_scan3() {
    int plane = blockIdx.y;
    int gi = blockIdx.x * 1024 + threadIdx.x;
    g_ev[plane * EP + gi] += g_part[plane * 256 + blockIdx.x];
}

// ---------------- sigmoid via degree-9 Taylor, binomial moment combine ----------------
__device__ __forceinline__ float sig_combine(float x, const float* A) {
    float xp[10];
    xp[0] = 1.0f;
    #pragma unroll
    for (int p = 1; p < 10; p++) xp[p] = xp[p - 1] * x;
    float B0 = A[0];
    float B1 = xp[1] * A[0] - A[1];
    float B3 = xp[3] * A[0] - 3.0f * xp[2] * A[1] + 3.0f * xp[1] * A[2] - A[3];
    float B5 = xp[5] * A[0] - 5.0f * xp[4] * A[1] + 10.0f * xp[3] * A[2]
             - 10.0f * xp[2] * A[3] + 5.0f * xp[1] * A[4] - A[5];
    float B7 = xp[7] * A[0] - 7.0f * xp[6] * A[1] + 21.0f * xp[5] * A[2]
             - 35.0f * xp[4] * A[3] + 35.0f * xp[3] * A[4] - 21.0f * xp[2] * A[5]
             + 7.0f * xp[1] * A[6] - A[7];
    float B9 = xp[9] * A[0] - 9.0f * xp[8] * A[1] + 36.0f * xp[7] * A[2]
             - 84.0f * xp[6] * A[3] + 126.0f * xp[5] * A[4] - 126.0f * xp[4] * A[5]
             + 84.0f * xp[3] * A[6] - 36.0f * xp[2] * A[7] + 9.0f * xp[1] * A[8] - A[9];
    return 0.5f * B0 + 0.25f * B1 - 0.0208333333f * B3 + 0.0020833333f * B5
         - 2.1081349e-4f * B7 + 2.1357107e-5f * B9;
}

// ---------------- subtree moments -> inside ----------------
__global__ void k_subtree() {
    int k = blockIdx.x * blockDim.x + threadIdx.x;
    if (k >= MACC) return;
    int a = L_ + k;
    unsigned int pd = g_pos[a], pu = g_pos[NN + a];
    float T[10];
    #pragma unroll
    for (int i = 0; i < 10; i++) T[i] = g_ev[i * EP + pu] - g_ev[i * EP + pd];
    g_ins[a] = sig_combine(g_alt[a], T);
}

// ---------------- final: out = outside + (leaf ? 0.5 : inside) ----------------
__global__ void k_final(float* __restrict__ out) {
    int n = blockIdx.x * blockDim.x + threadIdx.x;
    if (n >= NN) return;
    unsigned int pd = g_pos[n], pu = g_pos[NN + n];
    float sz = (float)((pu - pd + 3u) >> 2);
    float x  = g_alt[n];
    float A[10];
    float xp = 1.0f;
    #pragma unroll
    for (int i = 0; i < 10; i++) {
        A[i] = g_ev[(10 + i) * EP + pd] - sz * xp;   // strict ancestors only
        xp *= x;
    }
    float outside = sig_combine(x, A);
    out[n] = outside + (n < L_ ? 0.5f : g_ins[n]);
}

// ---------------- launch ----------------
extern "C" void kernel_launch(void* const* d_in, const int* in_sizes, int n_in,
                              void* d_out, int out_size) {
    const float* ew  = (const float*)d_in[0];
    const int*   src = (const int*)d_in[1];
    const int*   dst = (const int*)d_in[2];
    int M = in_sizes[0];   // 130560
    int nc = (M + CHUNK - 1) / CHUNK;   // 128

    k_init<<<NPAD / 256, 256>>>(M);

    // bucket sort (padded scatter -> scan -> warp-per-bucket sort + compact)
    k_bscatter<<<(M + 255) / 256, 256>>>(ew, M);
    k_bscan<<<1, 1024>>>();
    k_bsort<<<NB / 8, 256>>>(src, dst);

    // tree build: coarse labels -> parallel refinement -> per-chunk replay
    cudaFuncSetAttribute(k_phase1a, cudaFuncAttributeMaxDynamicSharedMemorySize, L_ * 2);
    cudaFuncSetAttribute(k_phase1b, cudaFuncAttributeMaxDynamicSharedMemorySize, L_ * 2);
    cudaFuncSetAttribute(k_phase2,  cudaFuncAttributeMaxDynamicSharedMemorySize, L_ * 2);
    k_phase1a<<<1, 1024, L_ * 2>>>(M);
    k_phase1b<<<NC1, 1024, L_ * 2>>>(M);
    k_phase2<<<nc, 1024, L_ * 2>>>(M);
    k_ascan<<<1, NCMAX>>>(nc);
    k_ascatter<<<(nc * CHUNK + 255) / 256, 256>>>(nc);

    // event sort (8192-wide tiles) + chain links
    k_esort_local_init<<<EVN / 8192, 1024>>>();
    for (int k = 16384; k <= EVN; k <<= 1) {
        for (int j = k >> 1; j >= 8192; j >>= 1)
            k_esort_global<<<(EVN / 2) / 256, 256>>>(j, k);
        k_esort_local_tail<<<EVN / 8192, 1024>>>(k);
    }
    k_vlink2<<<(2 * MACC + 255) / 256, 256>>>();

    // Euler tour + quad-hop list ranking (9 rounds) + fused final
    k_euler<<<(NN + 255) / 256, 256>>>();
    int s = 0;
    for (int r = 0; r < 9; r++) {
        k_rank4<<<(ELEN + 1 + 255) / 256, 256>>>(s);
        s = 1 - s;
    }
    k_rank_fin<<<(ELEN + 255) / 256, 256>>>(s);

    // path-sum scatter (sizes from Euler positions)
    k_pscatter<<<(NN + 255) / 256, 256>>>();

    // single scan round over all 20 planes
    {
        dim3 g1(256, 20); k_scan1<<<g1, 1024>>>();
        dim3 g2(1, 20);   k_scan2<<<g2, 256>>>();
        dim3 g3(256, 20); k_scan3<<<g3, 1024>>>();
    }

    k_subtree<<<(MACC + 255) / 256, 256>>>();
    k_final<<<(NN + 255) / 256, 256>>>((float*)d_out);
}

// round 14
// speedup vs baseline: 1.1028x; 1.1028x over previous
#include <cuda_runtime.h>
#include <cstdint>

// Problem constants (256x256 grid, 4-adjacency)
#define L_    65536      // leaves
#define NN    131071     // 2L-1 nodes
#define NPAD  262144     // 2^18 >= 130560 edges
#define MACC  (L_ - 1)   // accepted merges = 65535
#define FULLM 0xFFFFFFFFu
#define ELEN  (2 * NN)   // Euler elements = 262142
#define ESENT ELEN       // sentinel element
#define EP    262144     // Euler plane stride (pow2 >= ELEN)
#define CHUNK 1024       // edges per rank chunk (round-9/12 proven)
#define NCMAX 256
#define EVN   131072     // 2^17 >= 2*MACC event keys
#define NB    8192       // sort buckets
#define BCAP  64         // bucket capacity (Poisson(16); P(>64) ~ e^-40)
#define ETILE 16384      // esort local tile (64KB dynamic smem)

// ---------------- device scratch ----------------
__device__ unsigned long long g_keys2[NB * BCAP];  // padded bucket slots (4MB)
__device__ unsigned int   g_bcnt[NB];
__device__ unsigned int   g_boffs[NB];
__device__ unsigned long long g_esort[NPAD];  // (wbits<<32)|(v<<16)|u in rank order
__device__ unsigned int   g_lab[NPAD];        // endpoint labels at chunk start (a|b<<16)
__device__ unsigned int   g_recTmp[NPAD];     // per-chunk records
__device__ unsigned int   g_srcTmp[NPAD];     // per-chunk source edge index
__device__ unsigned int   g_acnt[NCMAX];
__device__ unsigned int   g_abase[NCMAX];
__device__ unsigned int g_rec[MACC];          // accepted i -> (win_min<<16)|lose_min
__device__ unsigned int g_ev2[EVN];           // event keys (v<<16)|k, then sorted
__device__ unsigned int g_parent[NN];
__device__ float        g_alt[NN];
__device__ unsigned int g_chw[MACC];          // child node on win-min side
__device__ unsigned int g_chl[MACC];          // child node on lose-min side
__device__ unsigned long long g_nd[2][ELEN + 1];  // Euler (nx | dd<<32), ping-pong
__device__ unsigned int g_pos[ELEN];          // Euler position
__device__ float        g_ev[20 * EP];        // planes 0..9 leaf moments, 10..19 path sums
__device__ float        g_part[20 * 256];     // scan block partials

// ---------------- init (fused zeroing) ----------------
__global__ void k_init(int M) {
    int i = blockIdx.x * blockDim.x + threadIdx.x;   // 262144 threads
    if (i < NN) { g_parent[i] = i; g_alt[i] = 0.0f; }
    if (i < NB) g_bcnt[i] = 0u;
    if (i >= 2 * MACC && i < EVN) g_ev2[i] = FULLM;
    #pragma unroll
    for (int p = 0; p < 10; p++) g_ev[p * EP + i] = 0.0f;   // planes 0..9 fully
    if (i >= ELEN) {                                        // planes 10..19: tail only
        #pragma unroll
        for (int p = 10; p < 20; p++) g_ev[p * EP + i] = 0.0f;
    }
}

// ---------------- bucket sort of (weight, idx) keys ----------------
__global__ void k_bscatter(const float* __restrict__ ew, int M) {
    int e = blockIdx.x * blockDim.x + threadIdx.x;
    if (e >= M) return;
    float w = ew[e];
    unsigned int b = min((unsigned int)(w * (float)NB), (unsigned int)(NB - 1));
    unsigned int slot = atomicAdd(&g_bcnt[b], 1u);
    if (slot < BCAP)
        g_keys2[b * BCAP + slot] = ((unsigned long long)__float_as_uint(w) << 32) | (unsigned int)e;
}

__global__ void k_bscan() {
    __shared__ unsigned int s[1024];
    __shared__ unsigned int s_run;
    int t = threadIdx.x;
    if (t == 0) s_run = 0u;
    __syncthreads();
    for (int c = 0; c < NB / 1024; c++) {
        unsigned int x = g_bcnt[c * 1024 + t];
        s[t] = x;
        __syncthreads();
        for (int off = 1; off < 1024; off <<= 1) {
            unsigned int y = (t >= off) ? s[t - off] : 0u;
            __syncthreads();
            s[t] += y;
            __syncthreads();
        }
        unsigned int run = s_run;
        g_boffs[c * 1024 + t] = run + s[t] - x;   // exclusive
        unsigned int tot = s[1023];
        __syncthreads();
        if (t == 0) s_run = run + tot;
        __syncthreads();
    }
}

// warp-per-bucket 64-wide bitonic (unique keys => stability); compacts + gathers endpoints
__global__ void __launch_bounds__(256) k_bsort(const int* __restrict__ src,
                                               const int* __restrict__ dst) {
    __shared__ unsigned long long s[8][BCAP];
    int wid  = threadIdx.x >> 5;
    int lane = threadIdx.x & 31;
    int b = blockIdx.x * 8 + wid;
    unsigned int cnt  = min(g_bcnt[b], (unsigned int)BCAP);
    unsigned int offs = g_boffs[b];
    s[wid][lane]      = (lane < (int)cnt)      ? g_keys2[b * BCAP + lane]      : ~0ull;
    s[wid][lane + 32] = (lane + 32 < (int)cnt) ? g_keys2[b * BCAP + lane + 32] : ~0ull;
    __syncwarp();
    #pragma unroll
    for (int k = 2; k <= BCAP; k <<= 1) {
        for (int j = k >> 1; j > 0; j >>= 1) {
            int pos = ((lane & ~(j - 1)) << 1) | (lane & (j - 1));
            bool asc = ((pos & k) == 0);
            unsigned long long x = s[wid][pos], y = s[wid][pos + j];
            if ((x > y) == asc) { s[wid][pos] = y; s[wid][pos + j] = x; }
            __syncwarp();
        }
    }
    for (int i = lane; i < (int)cnt; i += 32) {
        unsigned long long key = s[wid][i];
        unsigned int idx = (unsigned int)(key & 0xFFFFFFFFull);
        unsigned int wb  = (unsigned int)(key >> 32);
        unsigned int u = (unsigned int)src[idx];
        unsigned int v = (unsigned int)dst[idx];
        g_esort[offs + i] = ((unsigned long long)wb << 32) | (v << 16) | u;
    }
}

// ---------------- phase 1: chunk-boundary labels, UF in shared memory (round-12) ------
__device__ __forceinline__ unsigned int sfind(volatile unsigned short* uf, unsigned int x) {
    unsigned int p;
    while ((p = uf[x]) != x) {
        unsigned int gp = uf[p];
        if (gp != p) uf[x] = (unsigned short)gp;   // path halving (benign races)
        x = p;
    }
    return x;
}

__global__ void __launch_bounds__(1024) k_phase1(int M, int nc) {
    extern __shared__ unsigned short s_uf[];   // 65536 x u16 = 128KB
    int t = threadIdx.x;
    unsigned int* uf32 = (unsigned int*)s_uf;
    for (int i = t; i < L_ / 2; i += 1024)
        uf32[i] = (2u * i) | ((2u * i + 1u) << 16);
    __syncthreads();
    for (int c = 0; c < nc; c++) {
        int base = c * CHUNK;
        int n = min(CHUNK, M - base);
        for (int e = t; e < n; e += 1024) {
            unsigned long long cur = g_esort[base + e];
            unsigned int u = (unsigned int)cur & 0xFFFFu;
            unsigned int v = ((unsigned int)cur >> 16) & 0xFFFFu;
            unsigned int a = sfind(s_uf, u);
            unsigned int b = sfind(s_uf, v);
            g_lab[base + e] = a | (b << 16);
        }
        __syncthreads();
        for (int e = t; e < n; e += 1024) {
            unsigned long long cur = g_esort[base + e];
            unsigned int u = (unsigned int)cur & 0xFFFFu;
            unsigned int v = ((unsigned int)cur >> 16) & 0xFFFFu;
            for (;;) {
                unsigned int a = sfind(s_uf, u), b = sfind(s_uf, v);
                if (a == b) break;
                unsigned int hi = a > b ? a : b;
                unsigned int lo = a ^ b ^ hi;
                if (atomicCAS((unsigned short*)&s_uf[hi], (unsigned short)hi,
                              (unsigned short)lo) == (unsigned short)hi) break;
            }
        }
        __syncthreads();
    }
}

// ---------------- phase 2: independent serial replay per chunk (round-12) ----------
__device__ __forceinline__ unsigned int uf_find(volatile unsigned short* uf, unsigned int x) {
    unsigned int r = x, p;
    while ((p = uf[r]) != r) r = p;
    while ((p = uf[x]) != r) { uf[x] = (unsigned short)r; x = p; }
    return r;
}

__global__ void __launch_bounds__(1024) k_phase2(int M) {
    extern __shared__ unsigned short s_uf[];
    int c = blockIdx.x;
    int base = c * CHUNK;
    int n = min(CHUNK, M - base);
    unsigned int* uf32 = (unsigned int*)s_uf;
    for (int i = threadIdx.x; i < L_ / 2; i += blockDim.x)
        uf32[i] = (2u * i) | ((2u * i + 1u) << 16);
    __syncthreads();
    if (threadIdx.x == 0) {
        unsigned int cnt = 0;
        for (int e = 0; e < n; e++) {
            unsigned int lab = g_lab[base + e];
            unsigned int a = uf_find(s_uf, lab & 0xFFFFu);
            unsigned int b = uf_find(s_uf, lab >> 16);
            if (a == b) continue;
            unsigned int w = a < b ? a : b;
            unsigned int l = a ^ b ^ w;
            s_uf[l] = (unsigned short)w;
            g_recTmp[base + cnt] = (w << 16) | l;
            g_srcTmp[base + cnt] = (unsigned int)(base + e);
            cnt++;
        }
        g_acnt[c] = cnt;
    }
}

__global__ void k_ascan(int nc) {
    __shared__ unsigned int s[NCMAX];
    int t = threadIdx.x;
    unsigned int x = (t < nc) ? g_acnt[t] : 0u;
    s[t] = x;
    __syncthreads();
    for (int off = 1; off < NCMAX; off <<= 1) {
        unsigned int y = (t >= off) ? s[t - off] : 0u;
        __syncthreads();
        s[t] += y;
        __syncthreads();
    }
    if (t < nc) g_abase[t] = s[t] - x;   // exclusive
}

__global__ void k_ascatter(int nc) {
    int i = blockIdx.x * blockDim.x + threadIdx.x;
    int c = i / CHUNK, li = i % CHUNK;
    if (c >= nc || (unsigned int)li >= g_acnt[c]) return;
    unsigned int slot = g_abase[c] + (unsigned int)li;
    unsigned int rec = g_recTmp[c * CHUNK + li];
    g_rec[slot] = rec;
    unsigned int e = g_srcTmp[c * CHUNK + li];
    g_alt[L_ + slot] = __uint_as_float((unsigned int)(g_esort[e] >> 32));
    g_ev2[2 * slot]     = ((rec >> 16) << 16) | slot;       // win event
    g_ev2[2 * slot + 1] = ((rec & 0xFFFFu) << 16) | slot;   // lose event
}

// ---------------- bitonic sort, 32-bit event keys (16384-wide tiles, 64KB smem) -------
__global__ void __launch_bounds__(1024) k_esort_local_init() {
    extern __shared__ unsigned int s[];
    int base = blockIdx.x * ETILE;
    int t = threadIdx.x;
    #pragma unroll
    for (int i = 0; i < 16; i++) s[t + i * 1024] = g_ev2[base + t + i * 1024];
    __syncthreads();
    for (int k = 2; k <= ETILE; k <<= 1) {
        for (int j = k >> 1; j > 0; j >>= 1) {
            #pragma unroll
            for (int q = 0; q < 8; q++) {
                int p = t + q * 1024;
                int pos = ((p & ~(j - 1)) << 1) | (p & (j - 1));
                bool asc = (((base + pos) & k) == 0);
                unsigned int x = s[pos], y = s[pos + j];
                if ((x > y) == asc) { s[pos] = y; s[pos + j] = x; }
            }
            __syncthreads();
        }
    }
    #pragma unroll
    for (int i = 0; i < 16; i++) g_ev2[base + t + i * 1024] = s[t + i * 1024];
}

__global__ void k_esort_global(int j, int k) {
    int t = blockIdx.x * blockDim.x + threadIdx.x;
    int i = ((t & ~(j - 1)) << 1) | (t & (j - 1));
    int l = i + j;
    bool asc = ((i & k) == 0);
    unsigned int x = g_ev2[i], y = g_ev2[l];
    if ((x > y) == asc) { g_ev2[i] = y; g_ev2[l] = x; }
}

__global__ void __launch_bounds__(1024) k_esort_local_tail(int k) {
    extern __shared__ unsigned int s[];
    int base = blockIdx.x * ETILE;
    int t = threadIdx.x;
    #pragma unroll
    for (int i = 0; i < 16; i++) s[t + i * 1024] = g_ev2[base + t + i * 1024];
    __syncthreads();
    bool asc = ((base & k) == 0);   // k >= 32768 > tile: constant per tile
    for (int j = ETILE / 2; j > 0; j >>= 1) {
        #pragma unroll
        for (int q = 0; q < 8; q++) {
            int p = t + q * 1024;
            int pos = ((p & ~(j - 1)) << 1) | (p & (j - 1));
            unsigned int x = s[pos], y = s[pos + j];
            if ((x > y) == asc) { s[pos] = y; s[pos + j] = x; }
        }
        __syncthreads();
    }
    #pragma unroll
    for (int i = 0; i < 16; i++) g_ev2[base + t + i * 1024] = s[t + i * 1024];
}

// parallel chain links from sorted events
__global__ void k_vlink2() {
    int i = blockIdx.x * blockDim.x + threadIdx.x;
    if (i >= 2 * MACC) return;
    unsigned int key = g_ev2[i];
    unsigned int v = key >> 16, k = key & 0xFFFFu;
    unsigned int prevnode;
    if (i == 0 || (g_ev2[i - 1] >> 16) != v)
        prevnode = v;
    else
        prevnode = L_ + (g_ev2[i - 1] & 0xFFFFu);
    g_parent[prevnode] = L_ + k;
    if ((g_rec[k] >> 16) == v) g_chw[k] = prevnode;
    else                       g_chl[k] = prevnode;
}

// ---------------- Euler tour + list ranking (round-12 dual-hop) ----------------
__global__ void k_euler() {
    int n = blockIdx.x * blockDim.x + threadIdx.x;
    if (n >= NN) return;
    if (n == 0) g_nd[0][ESENT] = (unsigned long long)ESENT;   // dd=0 self-loop
    const unsigned long long ONE = 1ull << 32;
    if (n < L_) {
        g_nd[0][n] = (unsigned long long)(NN + n) | ONE;
    } else {
        int k = n - L_;
        unsigned int cw = g_chw[k], cl = g_chl[k];
        g_nd[0][n]       = (unsigned long long)cw | ONE;
        g_nd[0][NN + cw] = (unsigned long long)cl | ONE;
        g_nd[0][NN + cl] = (unsigned long long)(NN + n) | ONE;
    }
    if (n == NN - 1) g_nd[0][NN + n] = (unsigned long long)ESENT | ONE;
}

__global__ void k_rank(int s) {
    int e = blockIdx.x * blockDim.x + threadIdx.x;
    if (e > ELEN) return;
    unsigned long long x = g_nd[s][e];
    unsigned long long y = g_nd[s][(unsigned int)x];
    g_nd[1 - s][e] = (unsigned long long)(unsigned int)y + (((x >> 32) + (y >> 32)) << 32);
}

// final: positions; fuse leaf moment scatter (element id < L_ = down(leaf))
__global__ void k_rank_fin(int s) {
    int e = blockIdx.x * blockDim.x + threadIdx.x;
    if (e >= ELEN) return;
    unsigned long long x = g_nd[s][e];
    unsigned long long y = g_nd[s][(unsigned int)x];
    unsigned int dd = (unsigned int)((x >> 32) + (y >> 32));
    unsigned int p = (unsigned int)ELEN - dd;
    g_pos[e] = p;
    if (e < L_) {   // down(leaf e): scatter moments of alt(parent(leaf))
        float yv = g_alt[g_parent[e]];
        float pw = 1.0f;
        #pragma unroll
        for (int i = 0; i < 10; i++) { g_ev[i * EP + p] = pw; pw *= yv; }
    }
}

// planes 10..19: +val at down(n), -val at up(n); sz from Euler positions:
// leaves(n) = (pos_up - pos_down + 3) >> 2  (full binary tree)
__global__ void k_pscatter() {
    int n = blockIdx.x * blockDim.x + threadIdx.x;
    if (n >= NN) return;
    unsigned int pd = g_pos[n], pu = g_pos[NN + n];
    float sz = (float)((pu - pd + 3u) >> 2);
    float x  = g_alt[n];
    unsigned int p = g_parent[n];
    bool isroot = (p == (unsigned int)n);
    float y = g_alt[p];
    float xp = 1.0f, yp = 1.0f;
    #pragma unroll
    for (int i = 0; i < 10; i++) {
        float val = sz * (xp - (isroot ? 0.0f : yp));
        g_ev[(10 + i) * EP + pd] = val;
        g_ev[(10 + i) * EP + pu] = -val;
        xp *= x; yp *= y;
    }
}

// ---------------- 3-phase inclusive prefix scan (all 20 planes in one round) ----------
__global__ void k_scan1() {
    __shared__ float s[1024];
    int plane = blockIdx.y;
    int gi = blockIdx.x * 1024 + threadIdx.x;
    int t = threadIdx.x;
    float x = g_ev[plane * EP + gi];
    s[t] = x;
    __syncthreads();
    for (int off = 1; off < 1024; off <<= 1) {
        float y = (t >= off) ? s[t - off] : 0.0f;
        __syncthreads();
        s[t] += y;
        __syncthreads();
    }
    g_ev[plane * EP + gi] = s[t];
    if (t == 1023) g_part[plane * 256 + blockIdx.x] = s[1023];
}

__global__ void k_scan2() {
    __shared__ float s[256];
    int plane = blockIdx.y;
    int t = threadIdx.x;
    float x = g_part[plane * 256 + t];
    s[t] = x;
    __syncthreads();
    for (int off = 1; off < 256; off <<= 1) {
        float y = (t >= off) ? s[t - off] : 0.0f;
        __syncthreads();
        s[t] += y;
        __syncthreads();
    }
    g_part[plane * 256 + t] = s[t] - x;   // exclusive
}

__global__ void k_scan3() {
    int plane = blockIdx.y;
    int gi = blockIdx.x * 1024 + threadIdx.x;
    g_ev[plane * EP + gi] += g_part[plane * 256 + blockIdx.x];
}

// ---------------- sigmoid via degree-9 Taylor, binomial moment combine ----------------
__device__ __forceinline__ float sig_combine(float x, const float* A) {
    float xp[10];
    xp[0] = 1.0f;
    #pragma unroll
    for (int p = 1; p < 10; p++) xp[p] = xp[p - 1] * x;
    float B0 = A[0];
    float B1 = xp[1] * A[0] - A[1];
    float B3 = xp[3] * A[0] - 3.0f * xp[2] * A[1] + 3.0f * xp[1] * A[2] - A[3];
    float B5 = xp[5] * A[0] - 5.0f * xp[4] * A[1] + 10.0f * xp[3] * A[2]
             - 10.0f * xp[2] * A[3] + 5.0f * xp[1] * A[4] - A[5];
    float B7 = xp[7] * A[0] - 7.0f * xp[6] * A[1] + 21.0f * xp[5] * A[2]
             - 35.0f * xp[4] * A[3] + 35.0f * xp[3] * A[4] - 21.0f * xp[2] * A[5]
             + 7.0f * xp[1] * A[6] - A[7];
    float B9 = xp[9] * A[0] - 9.0f * xp[8] * A[1] + 36.0f * xp[7] * A[2]
             - 84.0f * xp[6] * A[3] + 126.0f * xp[5] * A[4] - 126.0f * xp[4] * A[5]
             + 84.0f * xp[3] * A[6] - 36.0f * xp[2] * A[7] + 9.0f * xp[1] * A[8] - A[9];
    return 0.5f * B0 + 0.25f * B1 - 0.0208333333f * B3 + 0.0020833333f * B5
         - 2.1081349e-4f * B7 + 2.1357107e-5f * B9;
}

// ---------------- final: out = outside + (leaf ? 0.5 : inside), fused ----------------
__global__ void k_final(float* __restrict__ out) {
    int n = blockIdx.x * blockDim.x + threadIdx.x;
    if (n >= NN) return;
    unsigned int pd = g_pos[n], pu = g_pos[NN + n];
    float sz = (float)((pu - pd + 3u) >> 2);
    float x  = g_alt[n];
    float A[10];
    float xp = 1.0f;
    #pragma unroll
    for (int i = 0; i < 10; i++) {
        A[i] = g_ev[(10 + i) * EP + pd] - sz * xp;   // strict ancestors only
        xp *= x;
    }
    float outside = sig_combine(x, A);
    float self;
    if (n < L_) {
        self = 0.5f;
    } else {   // inside from subtree moments (planes 0..9)
        float T[10];
        #pragma unroll
        for (int i = 0; i < 10; i++) T[i] = g_ev[i * EP + pu] - g_ev[i * EP + pd];
        self = sig_combine(x, T);
    }
    out[n] = outside + self;
}

// ---------------- launch ----------------
extern "C" void kernel_launch(void* const* d_in, const int* in_sizes, int n_in,
                              void* d_out, int out_size) {
    const float* ew  = (const float*)d_in[0];
    const int*   src = (const int*)d_in[1];
    const int*   dst = (const int*)d_in[2];
    int M = in_sizes[0];   // 130560
    int nc = (M + CHUNK - 1) / CHUNK;   // 128

    k_init<<<NPAD / 256, 256>>>(M);

    // bucket sort (padded scatter -> scan -> warp-per-bucket sort + compact)
    k_bscatter<<<(M + 255) / 256, 256>>>(ew, M);
    k_bscan<<<1, 1024>>>();
    k_bsort<<<NB / 8, 256>>>(src, dst);

    // tree build (round-12 proven path)
    cudaFuncSetAttribute(k_phase1, cudaFuncAttributeMaxDynamicSharedMemorySize, L_ * 2);
    cudaFuncSetAttribute(k_phase2, cudaFuncAttributeMaxDynamicSharedMemorySize, L_ * 2);
    k_phase1<<<1, 1024, L_ * 2>>>(M, nc);
    k_phase2<<<nc, 1024, L_ * 2>>>(M);
    k_ascan<<<1, NCMAX>>>(nc);
    k_ascatter<<<(nc * CHUNK + 255) / 256, 256>>>(nc);

    // event sort (16384-wide tiles) + chain links
    cudaFuncSetAttribute(k_esort_local_init, cudaFuncAttributeMaxDynamicSharedMemorySize,
                         ETILE * 4);
    cudaFuncSetAttribute(k_esort_local_tail, cudaFuncAttributeMaxDynamicSharedMemorySize,
                         ETILE * 4);
    k_esort_local_init<<<EVN / ETILE, 1024, ETILE * 4>>>();
    for (int k = 2 * ETILE; k <= EVN; k <<= 1) {
        for (int j = k >> 1; j >= ETILE; j >>= 1)
            k_esort_global<<<(EVN / 2) / 256, 256>>>(j, k);
        k_esort_local_tail<<<EVN / ETILE, 1024, ETILE * 4>>>(k);
    }
    k_vlink2<<<(2 * MACC + 255) / 256, 256>>>();

    // Euler tour + list ranking (round-12: 17 dual-hop rounds + fused final)
    k_euler<<<(NN + 255) / 256, 256>>>();
    int s = 0;
    for (int r = 0; r < 17; r++) {
        k_rank<<<(ELEN + 1 + 255) / 256, 256>>>(s);
        s = 1 - s;
    }
    k_rank_fin<<<(ELEN + 255) / 256, 256>>>(s);

    // path-sum scatter (sizes from Euler positions)
    k_pscatter<<<(NN + 255) / 256, 256>>>();

    // single scan round over all 20 planes
    {
        dim3 g1(256, 20); k_scan1<<<g1, 1024>>>();
        dim3 g2(1, 20);   k_scan2<<<g2, 256>>>();
        dim3 g3(256, 20); k_scan3<<<g3, 1024>>>();
    }

    k_final<<<(NN + 255) / 256, 256>>>((float*)d_out);
}

// round 15
// speedup vs baseline: 1.1750x; 1.0655x over previous
#include <cuda_runtime.h>
#include <cstdint>

// Problem constants (256x256 grid, 4-adjacency)
#define L_    65536      // leaves
#define NN    131071     // 2L-1 nodes
#define NPAD  262144     // 2^18 >= 130560 edges
#define MACC  (L_ - 1)   // accepted merges = 65535
#define FULLM 0xFFFFFFFFu
#define ELEN  (2 * NN)   // Euler elements = 262142
#define ESENT ELEN       // sentinel element
#define EP    262144     // Euler plane stride (pow2 >= ELEN)
#define CHUNK 1024       // edges per rank chunk (round-9/12 proven)
#define NCMAX 256
#define EVN   131072     // 2^17 >= 2*MACC event keys
#define NB    8192       // sort buckets
#define BCAP  64         // bucket capacity (Poisson(16); P(>64) ~ e^-40)

// ---------------- device scratch ----------------
__device__ unsigned long long g_keys2[NB * BCAP];  // padded bucket slots (4MB)
__device__ unsigned int   g_bcnt[NB];
__device__ unsigned int   g_boffs[NB];
__device__ unsigned long long g_esort[NPAD];  // (wbits<<32)|(v<<16)|u in rank order
__device__ unsigned int   g_lab[NPAD];        // endpoint labels at chunk start (a|b<<16)
__device__ unsigned int   g_recTmp[NPAD];     // per-chunk records
__device__ unsigned int   g_srcTmp[NPAD];     // per-chunk source edge index
__device__ unsigned int   g_acnt[NCMAX];
__device__ unsigned int   g_abase[NCMAX];
__device__ unsigned int g_rec[MACC];          // accepted i -> (win_min<<16)|lose_min
__device__ unsigned int g_ev2[EVN];           // event keys (v<<16)|k, then sorted
__device__ unsigned int g_parent[NN];
__device__ float        g_alt[NN];
__device__ unsigned int g_chw[MACC];          // child node on win-min side
__device__ unsigned int g_chl[MACC];          // child node on lose-min side
__device__ unsigned long long g_nd[2][ELEN + 1];  // Euler (nx | dd<<32), ping-pong
__device__ unsigned int g_pos[ELEN];          // Euler position
__device__ float        g_ev[20 * EP];        // planes 0..9 leaf moments, 10..19 path sums
__device__ float        g_part[20 * 256];     // scan block partials

// ---------------- init (fused zeroing) ----------------
__global__ void k_init(int M) {
    int i = blockIdx.x * blockDim.x + threadIdx.x;   // 262144 threads
    if (i < NN) { g_parent[i] = i; g_alt[i] = 0.0f; }
    if (i < NB) g_bcnt[i] = 0u;
    if (i >= 2 * MACC && i < EVN) g_ev2[i] = FULLM;
    #pragma unroll
    for (int p = 0; p < 10; p++) g_ev[p * EP + i] = 0.0f;   // planes 0..9 fully
    if (i >= ELEN) {                                        // planes 10..19: tail only
        #pragma unroll
        for (int p = 10; p < 20; p++) g_ev[p * EP + i] = 0.0f;
    }
}

// ---------------- bucket sort of (weight, idx) keys ----------------
__global__ void k_bscatter(const float* __restrict__ ew, int M) {
    int e = blockIdx.x * blockDim.x + threadIdx.x;
    if (e >= M) return;
    float w = ew[e];
    unsigned int b = min((unsigned int)(w * (float)NB), (unsigned int)(NB - 1));
    unsigned int slot = atomicAdd(&g_bcnt[b], 1u);
    if (slot < BCAP)
        g_keys2[b * BCAP + slot] = ((unsigned long long)__float_as_uint(w) << 32) | (unsigned int)e;
}

__global__ void k_bscan() {
    __shared__ unsigned int s[1024];
    __shared__ unsigned int s_run;
    int t = threadIdx.x;
    if (t == 0) s_run = 0u;
    __syncthreads();
    for (int c = 0; c < NB / 1024; c++) {
        unsigned int x = g_bcnt[c * 1024 + t];
        s[t] = x;
        __syncthreads();
        for (int off = 1; off < 1024; off <<= 1) {
            unsigned int y = (t >= off) ? s[t - off] : 0u;
            __syncthreads();
            s[t] += y;
            __syncthreads();
        }
        unsigned int run = s_run;
        g_boffs[c * 1024 + t] = run + s[t] - x;   // exclusive
        unsigned int tot = s[1023];
        __syncthreads();
        if (t == 0) s_run = run + tot;
        __syncthreads();
    }
}

// warp-per-bucket 64-wide bitonic (unique keys => stability); compacts + gathers endpoints
__global__ void __launch_bounds__(256) k_bsort(const int* __restrict__ src,
                                               const int* __restrict__ dst) {
    __shared__ unsigned long long s[8][BCAP];
    int wid  = threadIdx.x >> 5;
    int lane = threadIdx.x & 31;
    int b = blockIdx.x * 8 + wid;
    unsigned int cnt  = min(g_bcnt[b], (unsigned int)BCAP);
    unsigned int offs = g_boffs[b];
    s[wid][lane]      = (lane < (int)cnt)      ? g_keys2[b * BCAP + lane]      : ~0ull;
    s[wid][lane + 32] = (lane + 32 < (int)cnt) ? g_keys2[b * BCAP + lane + 32] : ~0ull;
    __syncwarp();
    #pragma unroll
    for (int k = 2; k <= BCAP; k <<= 1) {
        for (int j = k >> 1; j > 0; j >>= 1) {
            int pos = ((lane & ~(j - 1)) << 1) | (lane & (j - 1));
            bool asc = ((pos & k) == 0);
            unsigned long long x = s[wid][pos], y = s[wid][pos + j];
            if ((x > y) == asc) { s[wid][pos] = y; s[wid][pos + j] = x; }
            __syncwarp();
        }
    }
    for (int i = lane; i < (int)cnt; i += 32) {
        unsigned long long key = s[wid][i];
        unsigned int idx = (unsigned int)(key & 0xFFFFFFFFull);
        unsigned int wb  = (unsigned int)(key >> 32);
        unsigned int u = (unsigned int)src[idx];
        unsigned int v = (unsigned int)dst[idx];
        g_esort[offs + i] = ((unsigned long long)wb << 32) | (v << 16) | u;
    }
}

// ---------------- phase 1: chunk-boundary labels, UF in shared memory ----------------
__device__ __forceinline__ unsigned int sfind(volatile unsigned short* uf, unsigned int x) {
    unsigned int p;
    while ((p = uf[x]) != x) {
        unsigned int gp = uf[p];
        if (gp != p) uf[x] = (unsigned short)gp;   // path halving (benign races)
        x = p;
    }
    return x;
}

__global__ void __launch_bounds__(1024) k_phase1(int M, int nc) {
    extern __shared__ unsigned short s_uf[];   // 65536 x u16 = 128KB
    int t = threadIdx.x;
    unsigned int* uf32 = (unsigned int*)s_uf;
    for (int i = t; i < L_ / 2; i += 1024)
        uf32[i] = (2u * i) | ((2u * i + 1u) << 16);
    __syncthreads();
    for (int c = 0; c < nc; c++) {
        int base = c * CHUNK;
        int n = min(CHUNK, M - base);
        for (int e = t; e < n; e += 1024) {
            unsigned long long cur = g_esort[base + e];
            unsigned int u = (unsigned int)cur & 0xFFFFu;
            unsigned int v = ((unsigned int)cur >> 16) & 0xFFFFu;
            unsigned int a = sfind(s_uf, u);
            unsigned int b = sfind(s_uf, v);
            g_lab[base + e] = a | (b << 16);
        }
        __syncthreads();
        for (int e = t; e < n; e += 1024) {
            unsigned long long cur = g_esort[base + e];
            unsigned int u = (unsigned int)cur & 0xFFFFu;
            unsigned int v = ((unsigned int)cur >> 16) & 0xFFFFu;
            for (;;) {
                unsigned int a = sfind(s_uf, u), b = sfind(s_uf, v);
                if (a == b) break;
                unsigned int hi = a > b ? a : b;
                unsigned int lo = a ^ b ^ hi;
                if (atomicCAS((unsigned short*)&s_uf[hi], (unsigned short)hi,
                              (unsigned short)lo) == (unsigned short)hi) break;
            }
        }
        __syncthreads();
    }
}

// ---------------- phase 2: independent serial replay per chunk ----------------
__device__ __forceinline__ unsigned int uf_find(volatile unsigned short* uf, unsigned int x) {
    unsigned int r = x, p;
    while ((p = uf[r]) != r) r = p;
    while ((p = uf[x]) != r) { uf[x] = (unsigned short)r; x = p; }
    return r;
}

__global__ void __launch_bounds__(1024) k_phase2(int M) {
    extern __shared__ unsigned short s_uf[];
    int c = blockIdx.x;
    int base = c * CHUNK;
    int n = min(CHUNK, M - base);
    unsigned int* uf32 = (unsigned int*)s_uf;
    for (int i = threadIdx.x; i < L_ / 2; i += blockDim.x)
        uf32[i] = (2u * i) | ((2u * i + 1u) << 16);
    __syncthreads();
    if (threadIdx.x == 0) {
        unsigned int cnt = 0;
        for (int e = 0; e < n; e++) {
            unsigned int lab = g_lab[base + e];
            unsigned int a = uf_find(s_uf, lab & 0xFFFFu);
            unsigned int b = uf_find(s_uf, lab >> 16);
            if (a == b) continue;
            unsigned int w = a < b ? a : b;
            unsigned int l = a ^ b ^ w;
            s_uf[l] = (unsigned short)w;
            g_recTmp[base + cnt] = (w << 16) | l;
            g_srcTmp[base + cnt] = (unsigned int)(base + e);
            cnt++;
        }
        g_acnt[c] = cnt;
    }
}

__global__ void k_ascan(int nc) {
    __shared__ unsigned int s[NCMAX];
    int t = threadIdx.x;
    unsigned int x = (t < nc) ? g_acnt[t] : 0u;
    s[t] = x;
    __syncthreads();
    for (int off = 1; off < NCMAX; off <<= 1) {
        unsigned int y = (t >= off) ? s[t - off] : 0u;
        __syncthreads();
        s[t] += y;
        __syncthreads();
    }
    if (t < nc) g_abase[t] = s[t] - x;   // exclusive
}

__global__ void k_ascatter(int nc) {
    int i = blockIdx.x * blockDim.x + threadIdx.x;
    int c = i / CHUNK, li = i % CHUNK;
    if (c >= nc || (unsigned int)li >= g_acnt[c]) return;
    unsigned int slot = g_abase[c] + (unsigned int)li;
    unsigned int rec = g_recTmp[c * CHUNK + li];
    g_rec[slot] = rec;
    unsigned int e = g_srcTmp[c * CHUNK + li];
    g_alt[L_ + slot] = __uint_as_float((unsigned int)(g_esort[e] >> 32));
    g_ev2[2 * slot]     = ((rec >> 16) << 16) | slot;       // win event
    g_ev2[2 * slot + 1] = ((rec & 0xFFFFu) << 16) | slot;   // lose event
}

// ---------------- bitonic sort, 32-bit event keys (8192-wide tiles) ----------------
__global__ void __launch_bounds__(1024) k_esort_local_init() {
    __shared__ unsigned int s[8192];
    int base = blockIdx.x * 8192;
    int t = threadIdx.x;
    #pragma unroll
    for (int i = 0; i < 8; i++) s[t + i * 1024] = g_ev2[base + t + i * 1024];
    __syncthreads();
    for (int k = 2; k <= 8192; k <<= 1) {
        for (int j = k >> 1; j > 0; j >>= 1) {
            #pragma unroll
            for (int q = 0; q < 4; q++) {
                int p = t + q * 1024;
                int pos = ((p & ~(j - 1)) << 1) | (p & (j - 1));
                bool asc = (((base + pos) & k) == 0);
                unsigned int x = s[pos], y = s[pos + j];
                if ((x > y) == asc) { s[pos] = y; s[pos + j] = x; }
            }
            __syncthreads();
        }
    }
    #pragma unroll
    for (int i = 0; i < 8; i++) g_ev2[base + t + i * 1024] = s[t + i * 1024];
}

__global__ void k_esort_global(int j, int k) {
    int t = blockIdx.x * blockDim.x + threadIdx.x;
    int i = ((t & ~(j - 1)) << 1) | (t & (j - 1));
    int l = i + j;
    bool asc = ((i & k) == 0);
    unsigned int x = g_ev2[i], y = g_ev2[l];
    if ((x > y) == asc) { g_ev2[i] = y; g_ev2[l] = x; }
}

__global__ void __launch_bounds__(1024) k_esort_local_tail(int k) {
    __shared__ unsigned int s[8192];
    int base = blockIdx.x * 8192;
    int t = threadIdx.x;
    #pragma unroll
    for (int i = 0; i < 8; i++) s[t + i * 1024] = g_ev2[base + t + i * 1024];
    __syncthreads();
    bool asc = ((base & k) == 0);   // k >= 16384 > tile: constant per tile
    for (int j = 4096; j > 0; j >>= 1) {
        #pragma unroll
        for (int q = 0; q < 4; q++) {
            int p = t + q * 1024;
            int pos = ((p & ~(j - 1)) << 1) | (p & (j - 1));
            unsigned int x = s[pos], y = s[pos + j];
            if ((x > y) == asc) { s[pos] = y; s[pos + j] = x; }
        }
        __syncthreads();
    }
    #pragma unroll
    for (int i = 0; i < 8; i++) g_ev2[base + t + i * 1024] = s[t + i * 1024];
}

// parallel chain links from sorted events
__global__ void k_vlink2() {
    int i = blockIdx.x * blockDim.x + threadIdx.x;
    if (i >= 2 * MACC) return;
    unsigned int key = g_ev2[i];
    unsigned int v = key >> 16, k = key & 0xFFFFu;
    unsigned int prevnode;
    if (i == 0 || (g_ev2[i - 1] >> 16) != v)
        prevnode = v;
    else
        prevnode = L_ + (g_ev2[i - 1] & 0xFFFFu);
    g_parent[prevnode] = L_ + k;
    if ((g_rec[k] >> 16) == v) g_chw[k] = prevnode;
    else                       g_chl[k] = prevnode;
}

// ---------------- Euler tour + list ranking (nx,dd packed in u64) ----------------
__global__ void k_euler() {
    int n = blockIdx.x * blockDim.x + threadIdx.x;
    if (n >= NN) return;
    if (n == 0) g_nd[0][ESENT] = (unsigned long long)ESENT;   // dd=0 self-loop
    const unsigned long long ONE = 1ull << 32;
    if (n < L_) {
        g_nd[0][n] = (unsigned long long)(NN + n) | ONE;
    } else {
        int k = n - L_;
        unsigned int cw = g_chw[k], cl = g_chl[k];
        g_nd[0][n]       = (unsigned long long)cw | ONE;
        g_nd[0][NN + cw] = (unsigned long long)cl | ONE;
        g_nd[0][NN + cl] = (unsigned long long)(NN + n) | ONE;
    }
    if (n == NN - 1) g_nd[0][NN + n] = (unsigned long long)ESENT | ONE;
}

__global__ void k_rank(int s) {
    int e = blockIdx.x * blockDim.x + threadIdx.x;
    if (e > ELEN) return;
    unsigned long long x = g_nd[s][e];
    unsigned long long y = g_nd[s][(unsigned int)x];
    g_nd[1 - s][e] = (unsigned long long)(unsigned int)y + (((x >> 32) + (y >> 32)) << 32);
}

// final: positions; fuse leaf moment scatter (element id < L_ = down(leaf))
__global__ void k_rank_fin(int s) {
    int e = blockIdx.x * blockDim.x + threadIdx.x;
    if (e >= ELEN) return;
    unsigned long long x = g_nd[s][e];
    unsigned long long y = g_nd[s][(unsigned int)x];
    unsigned int dd = (unsigned int)((x >> 32) + (y >> 32));
    unsigned int p = (unsigned int)ELEN - dd;
    g_pos[e] = p;
    if (e < L_) {   // down(leaf e): scatter moments of alt(parent(leaf))
        float yv = g_alt[g_parent[e]];
        float pw = 1.0f;
        #pragma unroll
        for (int i = 0; i < 10; i++) { g_ev[i * EP + p] = pw; pw *= yv; }
    }
}

// planes 10..19: +val at down(n), -val at up(n); sz from Euler positions:
// leaves(n) = (pos_up - pos_down + 3) >> 2  (full binary tree)
__global__ void k_pscatter() {
    int n = blockIdx.x * blockDim.x + threadIdx.x;
    if (n >= NN) return;
    unsigned int pd = g_pos[n], pu = g_pos[NN + n];
    float sz = (float)((pu - pd + 3u) >> 2);
    float x  = g_alt[n];
    unsigned int p = g_parent[n];
    bool isroot = (p == (unsigned int)n);
    float y = g_alt[p];
    float xp = 1.0f, yp = 1.0f;
    #pragma unroll
    for (int i = 0; i < 10; i++) {
        float val = sz * (xp - (isroot ? 0.0f : yp));
        g_ev[(10 + i) * EP + pd] = val;
        g_ev[(10 + i) * EP + pu] = -val;
        xp *= x; yp *= y;
    }
}

// ---------------- 3-phase inclusive prefix scan (all 20 planes in one round) ----------
__global__ void k_scan1() {
    __shared__ float s[1024];
    int plane = blockIdx.y;
    int gi = blockIdx.x * 1024 + threadIdx.x;
    int t = threadIdx.x;
    float x = g_ev[plane * EP + gi];
    s[t] = x;
    __syncthreads();
    for (int off = 1; off < 1024; off <<= 1) {
        float y = (t >= off) ? s[t - off] : 0.0f;
        __syncthreads();
        s[t] += y;
        __syncthreads();
    }
    g_ev[plane * EP + gi] = s[t];
    if (t == 1023) g_part[plane * 256 + blockIdx.x] = s[1023];
}

__global__ void k_scan2() {
    __shared__ float s[256];
    int plane = blockIdx.y;
    int t = threadIdx.x;
    float x = g_part[plane * 256 + t];
    s[t] = x;
    __syncthreads();
    for (int off = 1; off < 256; off <<= 1) {
        float y = (t >= off) ? s[t - off] : 0.0f;
        __syncthreads();
        s[t] += y;
        __syncthreads();
    }
    g_part[plane * 256 + t] = s[t] - x;   // exclusive
}

__global__ void k_scan3() {
    int plane = blockIdx.y;
    int gi = blockIdx.x * 1024 + threadIdx.x;
    g_ev[plane * EP + gi] += g_part[plane * 256 + blockIdx.x];
}

// ---------------- sigmoid via degree-9 Taylor, binomial moment combine ----------------
__device__ __forceinline__ float sig_combine(float x, const float* A) {
    float xp[10];
    xp[0] = 1.0f;
    #pragma unroll
    for (int p = 1; p < 10; p++) xp[p] = xp[p - 1] * x;
    float B0 = A[0];
    float B1 = xp[1] * A[0] - A[1];
    float B3 = xp[3] * A[0] - 3.0f * xp[2] * A[1] + 3.0f * xp[1] * A[2] - A[3];
    float B5 = xp[5] * A[0] - 5.0f * xp[4] * A[1] + 10.0f * xp[3] * A[2]
             - 10.0f * xp[2] * A[3] + 5.0f * xp[1] * A[4] - A[5];
    float B7 = xp[7] * A[0] - 7.0f * xp[6] * A[1] + 21.0f * xp[5] * A[2]
             - 35.0f * xp[4] * A[3] + 35.0f * xp[3] * A[4] - 21.0f * xp[2] * A[5]
             + 7.0f * xp[1] * A[6] - A[7];
    float B9 = xp[9] * A[0] - 9.0f * xp[8] * A[1] + 36.0f * xp[7] * A[2]
             - 84.0f * xp[6] * A[3] + 126.0f * xp[5] * A[4] - 126.0f * xp[4] * A[5]
             + 84.0f * xp[3] * A[6] - 36.0f * xp[2] * A[7] + 9.0f * xp[1] * A[8] - A[9];
    return 0.5f * B0 + 0.25f * B1 - 0.0208333333f * B3 + 0.0020833333f * B5
         - 2.1081349e-4f * B7 + 2.1357107e-5f * B9;
}

// ---------------- final: out = outside + (leaf ? 0.5 : inside), fused ----------------
__global__ void k_final(float* __restrict__ out) {
    int n = blockIdx.x * blockDim.x + threadIdx.x;
    if (n >= NN) return;
    unsigned int pd = g_pos[n], pu = g_pos[NN + n];
    float sz = (float)((pu - pd + 3u) >> 2);
    float x  = g_alt[n];
    float A[10];
    float xp = 1.0f;
    #pragma unroll
    for (int i = 0; i < 10; i++) {
        A[i] = g_ev[(10 + i) * EP + pd] - sz * xp;   // strict ancestors only
        xp *= x;
    }
    float outside = sig_combine(x, A);
    float self;
    if (n < L_) {
        self = 0.5f;
    } else {   // inside from subtree moments (planes 0..9)
        float T[10];
        #pragma unroll
        for (int i = 0; i < 10; i++) T[i] = g_ev[i * EP + pu] - g_ev[i * EP + pd];
        self = sig_combine(x, T);
    }
    out[n] = outside + self;
}

// ---------------- launch ----------------
extern "C" void kernel_launch(void* const* d_in, const int* in_sizes, int n_in,
                              void* d_out, int out_size) {
    const float* ew  = (const float*)d_in[0];
    const int*   src = (const int*)d_in[1];
    const int*   dst = (const int*)d_in[2];
    int M = in_sizes[0];   // 130560
    int nc = (M + CHUNK - 1) / CHUNK;   // 128

    k_init<<<NPAD / 256, 256>>>(M);

    // bucket sort (padded scatter -> scan -> warp-per-bucket sort + compact)
    k_bscatter<<<(M + 255) / 256, 256>>>(ew, M);
    k_bscan<<<1, 1024>>>();
    k_bsort<<<NB / 8, 256>>>(src, dst);

    // tree build (round-12 proven path)
    cudaFuncSetAttribute(k_phase1, cudaFuncAttributeMaxDynamicSharedMemorySize, L_ * 2);
    cudaFuncSetAttribute(k_phase2, cudaFuncAttributeMaxDynamicSharedMemorySize, L_ * 2);
    k_phase1<<<1, 1024, L_ * 2>>>(M, nc);
    k_phase2<<<nc, 1024, L_ * 2>>>(M);
    k_ascan<<<1, NCMAX>>>(nc);
    k_ascatter<<<(nc * CHUNK + 255) / 256, 256>>>(nc);

    // event sort (8192-wide tiles, round-12 proven) + chain links
    k_esort_local_init<<<EVN / 8192, 1024>>>();
    for (int k = 16384; k <= EVN; k <<= 1) {
        for (int j = k >> 1; j >= 8192; j >>= 1)
            k_esort_global<<<(EVN / 2) / 256, 256>>>(j, k);
        k_esort_local_tail<<<EVN / 8192, 1024>>>(k);
    }
    k_vlink2<<<(2 * MACC + 255) / 256, 256>>>();

    // Euler tour + list ranking (17 dual-hop rounds + fused final)
    k_euler<<<(NN + 255) / 256, 256>>>();
    int s = 0;
    for (int r = 0; r < 17; r++) {
        k_rank<<<(ELEN + 1 + 255) / 256, 256>>>(s);
        s = 1 - s;
    }
    k_rank_fin<<<(ELEN + 255) / 256, 256>>>(s);

    // path-sum scatter (sizes from Euler positions)
    k_pscatter<<<(NN + 255) / 256, 256>>>();

    // single scan round over all 20 planes
    {
        dim3 g1(256, 20); k_scan1<<<g1, 1024>>>();
        dim3 g2(1, 20);   k_scan2<<<g2, 256>>>();
        dim3 g3(256, 20); k_scan3<<<g3, 1024>>>();
    }

    k_final<<<(NN + 255) / 256, 256>>>((float*)d_out);
}

// round 16
// speedup vs baseline: 1.1950x; 1.0171x over previous
#include <cuda_runtime.h>
#include <cstdint>

// Problem constants (256x256 grid, 4-adjacency)
#define L_    65536      // leaves
#define NN    131071     // 2L-1 nodes
#define NPAD  262144     // 2^18 >= 130560 edges
#define MACC  (L_ - 1)   // accepted merges = 65535
#define FULLM 0xFFFFFFFFu
#define ELEN  (2 * NN)   // Euler elements = 262142
#define ESENT ELEN       // sentinel element
#define EP    262144     // Euler plane stride (pow2 >= ELEN)
#define CHUNK 1024       // edges per rank chunk (round-9/12 proven)
#define NCMAX 256
#define EVN   131072     // 2^17 >= 2*MACC event keys
#define NB    8192       // sort buckets
#define BCAP  64         // bucket capacity (Poisson(16); P(>64) ~ e^-40)

// ---------------- device scratch ----------------
__device__ unsigned long long g_keys2[NB * BCAP];  // padded bucket slots (4MB)
__device__ unsigned int   g_bcnt[NB];
__device__ unsigned int   g_boffs[NB];
__device__ unsigned long long g_esort[NPAD];  // (wbits<<32)|(v<<16)|u in rank order
__device__ unsigned int   g_lab[NPAD];        // endpoint labels at chunk start (a|b<<16)
__device__ unsigned int   g_recTmp[NPAD];     // per-chunk records
__device__ unsigned int   g_srcTmp[NPAD];     // per-chunk source edge index
__device__ unsigned int   g_acnt[NCMAX];
__device__ unsigned int   g_abase[NCMAX];
__device__ unsigned int g_rec[MACC];          // accepted i -> (win_min<<16)|lose_min
__device__ unsigned int g_ev2[EVN];           // event keys (v<<16)|k, then sorted
__device__ unsigned int g_parent[NN];
__device__ float        g_alt[NN];
__device__ unsigned int g_chw[MACC];          // child node on win-min side
__device__ unsigned int g_chl[MACC];          // child node on lose-min side
__device__ unsigned long long g_nd[2][ELEN + 1];  // Euler (nx | dd<<32), ping-pong
__device__ unsigned int g_pos[ELEN];          // Euler position
__device__ float        g_ev[20 * EP];        // planes 0..9 leaf moments, 10..19 path sums
__device__ float        g_part[20 * 256];     // scan block partials

// ---------------- init (fused zeroing) ----------------
__global__ void k_init(int M) {
    int i = blockIdx.x * blockDim.x + threadIdx.x;   // 262144 threads
    if (i < NN) { g_parent[i] = i; g_alt[i] = 0.0f; }
    if (i < NB) g_bcnt[i] = 0u;
    if (i >= 2 * MACC && i < EVN) g_ev2[i] = FULLM;
    #pragma unroll
    for (int p = 0; p < 10; p++) g_ev[p * EP + i] = 0.0f;   // planes 0..9 fully
    if (i >= ELEN) {                                        // planes 10..19: tail only
        #pragma unroll
        for (int p = 10; p < 20; p++) g_ev[p * EP + i] = 0.0f;
    }
}

// ---------------- bucket sort of (weight, idx) keys ----------------
__global__ void k_bscatter(const float* __restrict__ ew, int M) {
    int e = blockIdx.x * blockDim.x + threadIdx.x;
    if (e >= M) return;
    float w = ew[e];
    unsigned int b = min((unsigned int)(w * (float)NB), (unsigned int)(NB - 1));
    unsigned int slot = atomicAdd(&g_bcnt[b], 1u);
    if (slot < BCAP)
        g_keys2[b * BCAP + slot] = ((unsigned long long)__float_as_uint(w) << 32) | (unsigned int)e;
}

__global__ void k_bscan() {
    __shared__ unsigned int s[1024];
    __shared__ unsigned int s_run;
    int t = threadIdx.x;
    if (t == 0) s_run = 0u;
    __syncthreads();
    for (int c = 0; c < NB / 1024; c++) {
        unsigned int x = g_bcnt[c * 1024 + t];
        s[t] = x;
        __syncthreads();
        for (int off = 1; off < 1024; off <<= 1) {
            unsigned int y = (t >= off) ? s[t - off] : 0u;
            __syncthreads();
            s[t] += y;
            __syncthreads();
        }
        unsigned int run = s_run;
        g_boffs[c * 1024 + t] = run + s[t] - x;   // exclusive
        unsigned int tot = s[1023];
        __syncthreads();
        if (t == 0) s_run = run + tot;
        __syncthreads();
    }
}

// warp-per-bucket 64-wide bitonic (unique keys => stability); compacts + gathers endpoints
__global__ void __launch_bounds__(256) k_bsort(const int* __restrict__ src,
                                               const int* __restrict__ dst) {
    __shared__ unsigned long long s[8][BCAP];
    int wid  = threadIdx.x >> 5;
    int lane = threadIdx.x & 31;
    int b = blockIdx.x * 8 + wid;
    unsigned int cnt  = min(g_bcnt[b], (unsigned int)BCAP);
    unsigned int offs = g_boffs[b];
    s[wid][lane]      = (lane < (int)cnt)      ? g_keys2[b * BCAP + lane]      : ~0ull;
    s[wid][lane + 32] = (lane + 32 < (int)cnt) ? g_keys2[b * BCAP + lane + 32] : ~0ull;
    __syncwarp();
    #pragma unroll
    for (int k = 2; k <= BCAP; k <<= 1) {
        for (int j = k >> 1; j > 0; j >>= 1) {
            int pos = ((lane & ~(j - 1)) << 1) | (lane & (j - 1));
            bool asc = ((pos & k) == 0);
            unsigned long long x = s[wid][pos], y = s[wid][pos + j];
            if ((x > y) == asc) { s[wid][pos] = y; s[wid][pos + j] = x; }
            __syncwarp();
        }
    }
    for (int i = lane; i < (int)cnt; i += 32) {
        unsigned long long key = s[wid][i];
        unsigned int idx = (unsigned int)(key & 0xFFFFFFFFull);
        unsigned int wb  = (unsigned int)(key >> 32);
        unsigned int u = (unsigned int)src[idx];
        unsigned int v = (unsigned int)dst[idx];
        g_esort[offs + i] = ((unsigned long long)wb << 32) | (v << 16) | u;
    }
}

// ---------------- phase 1: chunk-boundary labels, UF in shared memory ----------------
__device__ __forceinline__ unsigned int sfind(volatile unsigned short* uf, unsigned int x) {
    unsigned int p;
    while ((p = uf[x]) != x) {
        unsigned int gp = uf[p];
        if (gp != p) uf[x] = (unsigned short)gp;   // path halving (benign races)
        x = p;
    }
    return x;
}

__global__ void __launch_bounds__(1024) k_phase1(int M, int nc) {
    extern __shared__ unsigned short s_uf[];   // 65536 x u16 = 128KB
    int t = threadIdx.x;
    unsigned int* uf32 = (unsigned int*)s_uf;
    for (int i = t; i < L_ / 2; i += 1024)
        uf32[i] = (2u * i) | ((2u * i + 1u) << 16);
    __syncthreads();
    for (int c = 0; c < nc; c++) {
        int base = c * CHUNK;
        int n = min(CHUNK, M - base);
        for (int e = t; e < n; e += 1024) {
            unsigned long long cur = g_esort[base + e];
            unsigned int u = (unsigned int)cur & 0xFFFFu;
            unsigned int v = ((unsigned int)cur >> 16) & 0xFFFFu;
            unsigned int a = sfind(s_uf, u);
            unsigned int b = sfind(s_uf, v);
            g_lab[base + e] = a | (b << 16);
        }
        __syncthreads();
        for (int e = t; e < n; e += 1024) {
            unsigned long long cur = g_esort[base + e];
            unsigned int u = (unsigned int)cur & 0xFFFFu;
            unsigned int v = ((unsigned int)cur >> 16) & 0xFFFFu;
            for (;;) {
                unsigned int a = sfind(s_uf, u), b = sfind(s_uf, v);
                if (a == b) break;
                unsigned int hi = a > b ? a : b;
                unsigned int lo = a ^ b ^ hi;
                if (atomicCAS((unsigned short*)&s_uf[hi], (unsigned short)hi,
                              (unsigned short)lo) == (unsigned short)hi) break;
            }
        }
        __syncthreads();
    }
}

// ---------------- phase 2: independent serial replay per chunk ----------------
__device__ __forceinline__ unsigned int uf_find(volatile unsigned short* uf, unsigned int x) {
    unsigned int r = x, p;
    while ((p = uf[r]) != r) r = p;
    while ((p = uf[x]) != r) { uf[x] = (unsigned short)r; x = p; }
    return r;
}

__global__ void __launch_bounds__(1024) k_phase2(int M) {
    extern __shared__ unsigned short s_uf[];
    int c = blockIdx.x;
    int base = c * CHUNK;
    int n = min(CHUNK, M - base);
    unsigned int* uf32 = (unsigned int*)s_uf;
    for (int i = threadIdx.x; i < L_ / 2; i += blockDim.x)
        uf32[i] = (2u * i) | ((2u * i + 1u) << 16);
    __syncthreads();
    if (threadIdx.x == 0) {
        unsigned int cnt = 0;
        for (int e = 0; e < n; e++) {
            unsigned int lab = g_lab[base + e];
            unsigned int a = uf_find(s_uf, lab & 0xFFFFu);
            unsigned int b = uf_find(s_uf, lab >> 16);
            if (a == b) continue;
            unsigned int w = a < b ? a : b;
            unsigned int l = a ^ b ^ w;
            s_uf[l] = (unsigned short)w;
            g_recTmp[base + cnt] = (w << 16) | l;
            g_srcTmp[base + cnt] = (unsigned int)(base + e);
            cnt++;
        }
        g_acnt[c] = cnt;
    }
}

__global__ void k_ascan(int nc) {
    __shared__ unsigned int s[NCMAX];
    int t = threadIdx.x;
    unsigned int x = (t < nc) ? g_acnt[t] : 0u;
    s[t] = x;
    __syncthreads();
    for (int off = 1; off < NCMAX; off <<= 1) {
        unsigned int y = (t >= off) ? s[t - off] : 0u;
        __syncthreads();
        s[t] += y;
        __syncthreads();
    }
    if (t < nc) g_abase[t] = s[t] - x;   // exclusive
}

__global__ void k_ascatter(int nc) {
    int i = blockIdx.x * blockDim.x + threadIdx.x;
    int c = i / CHUNK, li = i % CHUNK;
    if (c >= nc || (unsigned int)li >= g_acnt[c]) return;
    unsigned int slot = g_abase[c] + (unsigned int)li;
    unsigned int rec = g_recTmp[c * CHUNK + li];
    g_rec[slot] = rec;
    unsigned int e = g_srcTmp[c * CHUNK + li];
    g_alt[L_ + slot] = __uint_as_float((unsigned int)(g_esort[e] >> 32));
    g_ev2[2 * slot]     = ((rec >> 16) << 16) | slot;       // win event
    g_ev2[2 * slot + 1] = ((rec & 0xFFFFu) << 16) | slot;   // lose event
}

// ---------------- bitonic sort, 32-bit event keys (8192-wide tiles) ----------------
__global__ void __launch_bounds__(1024) k_esort_local_init() {
    __shared__ unsigned int s[8192];
    int base = blockIdx.x * 8192;
    int t = threadIdx.x;
    #pragma unroll
    for (int i = 0; i < 8; i++) s[t + i * 1024] = g_ev2[base + t + i * 1024];
    __syncthreads();
    for (int k = 2; k <= 8192; k <<= 1) {
        for (int j = k >> 1; j > 0; j >>= 1) {
            #pragma unroll
            for (int q = 0; q < 4; q++) {
                int p = t + q * 1024;
                int pos = ((p & ~(j - 1)) << 1) | (p & (j - 1));
                bool asc = (((base + pos) & k) == 0);
                unsigned int x = s[pos], y = s[pos + j];
                if ((x > y) == asc) { s[pos] = y; s[pos + j] = x; }
            }
            __syncthreads();
        }
    }
    #pragma unroll
    for (int i = 0; i < 8; i++) g_ev2[base + t + i * 1024] = s[t + i * 1024];
}

__global__ void k_esort_global(int j, int k) {
    int t = blockIdx.x * blockDim.x + threadIdx.x;
    int i = ((t & ~(j - 1)) << 1) | (t & (j - 1));
    int l = i + j;
    bool asc = ((i & k) == 0);
    unsigned int x = g_ev2[i], y = g_ev2[l];
    if ((x > y) == asc) { g_ev2[i] = y; g_ev2[l] = x; }
}

__global__ void __launch_bounds__(1024) k_esort_local_tail(int k) {
    __shared__ unsigned int s[8192];
    int base = blockIdx.x * 8192;
    int t = threadIdx.x;
    #pragma unroll
    for (int i = 0; i < 8; i++) s[t + i * 1024] = g_ev2[base + t + i * 1024];
    __syncthreads();
    bool asc = ((base & k) == 0);   // k >= 16384 > tile: constant per tile
    for (int j = 4096; j > 0; j >>= 1) {
        #pragma unroll
        for (int q = 0; q < 4; q++) {
            int p = t + q * 1024;
            int pos = ((p & ~(j - 1)) << 1) | (p & (j - 1));
            unsigned int x = s[pos], y = s[pos + j];
            if ((x > y) == asc) { s[pos] = y; s[pos + j] = x; }
        }
        __syncthreads();
    }
    #pragma unroll
    for (int i = 0; i < 8; i++) g_ev2[base + t + i * 1024] = s[t + i * 1024];
}

// parallel chain links from sorted events
__global__ void k_vlink2() {
    int i = blockIdx.x * blockDim.x + threadIdx.x;
    if (i >= 2 * MACC) return;
    unsigned int key = g_ev2[i];
    unsigned int v = key >> 16, k = key & 0xFFFFu;
    unsigned int prevnode;
    if (i == 0 || (g_ev2[i - 1] >> 16) != v)
        prevnode = v;
    else
        prevnode = L_ + (g_ev2[i - 1] & 0xFFFFu);
    g_parent[prevnode] = L_ + k;
    if ((g_rec[k] >> 16) == v) g_chw[k] = prevnode;
    else                       g_chl[k] = prevnode;
}

// ---------------- Euler tour + list ranking (quad-hop doubling) ----------------
__global__ void k_euler() {
    int n = blockIdx.x * blockDim.x + threadIdx.x;
    if (n >= NN) return;
    if (n == 0) g_nd[0][ESENT] = (unsigned long long)ESENT;   // dd=0 self-loop
    const unsigned long long ONE = 1ull << 32;
    if (n < L_) {
        g_nd[0][n] = (unsigned long long)(NN + n) | ONE;
    } else {
        int k = n - L_;
        unsigned int cw = g_chw[k], cl = g_chl[k];
        g_nd[0][n]       = (unsigned long long)cw | ONE;
        g_nd[0][NN + cw] = (unsigned long long)cl | ONE;
        g_nd[0][NN + cl] = (unsigned long long)(NN + n) | ONE;
    }
    if (n == NN - 1) g_nd[0][NN + n] = (unsigned long long)ESENT | ONE;
}

// quad-hop: one launch = two doubling rounds (4 hops). 4^9 = 2^18 >= ELEN+1 list length.
// Sentinel self-loop (dd=0) makes over-doubling a no-op.
__global__ void k_rank4(int s) {
    int e = blockIdx.x * blockDim.x + threadIdx.x;
    if (e > ELEN) return;
    unsigned long long a = g_nd[s][e];
    unsigned long long b = g_nd[s][(unsigned int)a];
    unsigned long long c = g_nd[s][(unsigned int)b];
    unsigned long long d = g_nd[s][(unsigned int)c];
    unsigned long long dd = (a >> 32) + (b >> 32) + (c >> 32) + (d >> 32);
    g_nd[1 - s][e] = (unsigned long long)(unsigned int)d | (dd << 32);
}

// final: positions; fuse leaf moment scatter (element id < L_ = down(leaf))
__global__ void k_rank_fin(int s) {
    int e = blockIdx.x * blockDim.x + threadIdx.x;
    if (e >= ELEN) return;
    unsigned long long x = g_nd[s][e];
    unsigned long long y = g_nd[s][(unsigned int)x];
    unsigned int dd = (unsigned int)((x >> 32) + (y >> 32));
    unsigned int p = (unsigned int)ELEN - dd;
    g_pos[e] = p;
    if (e < L_) {   // down(leaf e): scatter moments of alt(parent(leaf))
        float yv = g_alt[g_parent[e]];
        float pw = 1.0f;
        #pragma unroll
        for (int i = 0; i < 10; i++) { g_ev[i * EP + p] = pw; pw *= yv; }
    }
}

// planes 10..19: +val at down(n), -val at up(n); sz from Euler positions:
// leaves(n) = (pos_up - pos_down + 3) >> 2  (full binary tree)
__global__ void k_pscatter() {
    int n = blockIdx.x * blockDim.x + threadIdx.x;
    if (n >= NN) return;
    unsigned int pd = g_pos[n], pu = g_pos[NN + n];
    float sz = (float)((pu - pd + 3u) >> 2);
    float x  = g_alt[n];
    unsigned int p = g_parent[n];
    bool isroot = (p == (unsigned int)n);
    float y = g_alt[p];
    float xp = 1.0f, yp = 1.0f;
    #pragma unroll
    for (int i = 0; i < 10; i++) {
        float val = sz * (xp - (isroot ? 0.0f : yp));
        g_ev[(10 + i) * EP + pd] = val;
        g_ev[(10 + i) * EP + pu] = -val;
        xp *= x; yp *= y;
    }
}

// ---------------- 3-phase inclusive prefix scan (all 20 planes in one round) ----------
__global__ void k_scan1() {
    __shared__ float s[1024];
    int plane = blockIdx.y;
    int gi = blockIdx.x * 1024 + threadIdx.x;
    int t = threadIdx.x;
    float x = g_ev[plane * EP + gi];
    s[t] = x;
    __syncthreads();
    for (int off = 1; off < 1024; off <<= 1) {
        float y = (t >= off) ? s[t - off] : 0.0f;
        __syncthreads();
        s[t] += y;
        __syncthreads();
    }
    g_ev[plane * EP + gi] = s[t];
    if (t == 1023) g_part[plane * 256 + blockIdx.x] = s[1023];
}

__global__ void k_scan2() {
    __shared__ float s[256];
    int plane = blockIdx.y;
    int t = threadIdx.x;
    float x = g_part[plane * 256 + t];
    s[t] = x;
    __syncthreads();
    for (int off = 1; off < 256; off <<= 1) {
        float y = (t >= off) ? s[t - off] : 0.0f;
        __syncthreads();
        s[t] += y;
        __syncthreads();
    }
    g_part[plane * 256 + t] = s[t] - x;   // exclusive
}

__global__ void k_scan3() {
    int plane = blockIdx.y;
    int gi = blockIdx.x * 1024 + threadIdx.x;
    g_ev[plane * EP + gi] += g_part[plane * 256 + blockIdx.x];
}

// ---------------- sigmoid via degree-9 Taylor, binomial moment combine ----------------
__device__ __forceinline__ float sig_combine(float x, const float* A) {
    float xp[10];
    xp[0] = 1.0f;
    #pragma unroll
    for (int p = 1; p < 10; p++) xp[p] = xp[p - 1] * x;
    float B0 = A[0];
    float B1 = xp[1] * A[0] - A[1];
    float B3 = xp[3] * A[0] - 3.0f * xp[2] * A[1] + 3.0f * xp[1] * A[2] - A[3];
    float B5 = xp[5] * A[0] - 5.0f * xp[4] * A[1] + 10.0f * xp[3] * A[2]
             - 10.0f * xp[2] * A[3] + 5.0f * xp[1] * A[4] - A[5];
    float B7 = xp[7] * A[0] - 7.0f * xp[6] * A[1] + 21.0f * xp[5] * A[2]
             - 35.0f * xp[4] * A[3] + 35.0f * xp[3] * A[4] - 21.0f * xp[2] * A[5]
             + 7.0f * xp[1] * A[6] - A[7];
    float B9 = xp[9] * A[0] - 9.0f * xp[8] * A[1] + 36.0f * xp[7] * A[2]
             - 84.0f * xp[6] * A[3] + 126.0f * xp[5] * A[4] - 126.0f * xp[4] * A[5]
             + 84.0f * xp[3] * A[6] - 36.0f * xp[2] * A[7] + 9.0f * xp[1] * A[8] - A[9];
    return 0.5f * B0 + 0.25f * B1 - 0.0208333333f * B3 + 0.0020833333f * B5
         - 2.1081349e-4f * B7 + 2.1357107e-5f * B9;
}

// ---------------- final: out = outside + (leaf ? 0.5 : inside), fused ----------------
__global__ void k_final(float* __restrict__ out) {
    int n = blockIdx.x * blockDim.x + threadIdx.x;
    if (n >= NN) return;
    unsigned int pd = g_pos[n], pu = g_pos[NN + n];
    float sz = (float)((pu - pd + 3u) >> 2);
    float x  = g_alt[n];
    float A[10];
    float xp = 1.0f;
    #pragma unroll
    for (int i = 0; i < 10; i++) {
        A[i] = g_ev[(10 + i) * EP + pd] - sz * xp;   // strict ancestors only
        xp *= x;
    }
    float outside = sig_combine(x, A);
    float self;
    if (n < L_) {
        self = 0.5f;
    } else {   // inside from subtree moments (planes 0..9)
        float T[10];
        #pragma unroll
        for (int i = 0; i < 10; i++) T[i] = g_ev[i * EP + pu] - g_ev[i * EP + pd];
        self = sig_combine(x, T);
    }
    out[n] = outside + self;
}

// ---------------- launch ----------------
extern "C" void kernel_launch(void* const* d_in, const int* in_sizes, int n_in,
                              void* d_out, int out_size) {
    const float* ew  = (const float*)d_in[0];
    const int*   src = (const int*)d_in[1];
    const int*   dst = (const int*)d_in[2];
    int M = in_sizes[0];   // 130560
    int nc = (M + CHUNK - 1) / CHUNK;   // 128

    k_init<<<NPAD / 256, 256>>>(M);

    // bucket sort (padded scatter -> scan -> warp-per-bucket sort + compact)
    k_bscatter<<<(M + 255) / 256, 256>>>(ew, M);
    k_bscan<<<1, 1024>>>();
    k_bsort<<<NB / 8, 256>>>(src, dst);

    // tree build (round-12 proven path)
    cudaFuncSetAttribute(k_phase1, cudaFuncAttributeMaxDynamicSharedMemorySize, L_ * 2);
    cudaFuncSetAttribute(k_phase2, cudaFuncAttributeMaxDynamicSharedMemorySize, L_ * 2);
    k_phase1<<<1, 1024, L_ * 2>>>(M, nc);
    k_phase2<<<nc, 1024, L_ * 2>>>(M);
    k_ascan<<<1, NCMAX>>>(nc);
    k_ascatter<<<(nc * CHUNK + 255) / 256, 256>>>(nc);

    // event sort (8192-wide tiles, round-12 proven) + chain links
    k_esort_local_init<<<EVN / 8192, 1024>>>();
    for (int k = 16384; k <= EVN; k <<= 1) {
        for (int j = k >> 1; j >= 8192; j >>= 1)
            k_esort_global<<<(EVN / 2) / 256, 256>>>(j, k);
        k_esort_local_tail<<<EVN / 8192, 1024>>>(k);
    }
    k_vlink2<<<(2 * MACC + 255) / 256, 256>>>();

    // Euler tour + quad-hop list ranking (9 rounds) + fused final
    k_euler<<<(NN + 255) / 256, 256>>>();
    int s = 0;
    for (int r = 0; r < 9; r++) {
        k_rank4<<<(ELEN + 1 + 255) / 256, 256>>>(s);
        s = 1 - s;
    }
    k_rank_fin<<<(ELEN + 255) / 256, 256>>>(s);

    // path-sum scatter (sizes from Euler positions)
    k_pscatter<<<(NN + 255) / 256, 256>>>();

    // single scan round over all 20 planes
    {
        dim3 g1(256, 20); k_scan1<<<g1, 1024>>>();
        dim3 g2(1, 20);   k_scan2<<<g2, 256>>>();
        dim3 g3(256, 20); k_scan3<<<g3, 1024>>>();
    }

    k_final<<<(NN + 255) / 256, 256>>>((float*)d_out);
}

// round 17
// speedup vs baseline: 1.2100x; 1.0125x over previous
#include <cuda_runtime.h>
#include <cstdint>

// Problem constants (256x256 grid, 4-adjacency)
#define L_    65536      // leaves
#define NN    131071     // 2L-1 nodes
#define NPAD  262144     // 2^18 >= 130560 edges
#define MACC  (L_ - 1)   // accepted merges = 65535
#define FULLM 0xFFFFFFFFu
#define ELEN  (2 * NN)   // Euler elements = 262142
#define ESENT ELEN       // sentinel element
#define EP    262144     // Euler plane stride (pow2 >= ELEN)
#define CHUNK 1024       // edges per rank chunk (round-9/12 proven)
#define NCMAX 256
#define EVN   131072     // 2^17 >= 2*MACC event keys
#define NB    8192       // sort buckets
#define BCAP  64         // bucket capacity (Poisson(16); P(>64) ~ e^-40)

// ---------------- device scratch ----------------
__device__ unsigned long long g_keys2[NB * BCAP];  // padded bucket slots (4MB)
__device__ unsigned int   g_bcnt[NB];
__device__ unsigned int   g_boffs[NB];
__device__ unsigned long long g_esort[NPAD];  // (wbits<<32)|(v<<16)|u in rank order
__device__ unsigned int   g_lab[NPAD];        // endpoint labels at chunk start (a|b<<16)
__device__ unsigned int   g_recTmp[NPAD];     // per-chunk records
__device__ unsigned int   g_srcTmp[NPAD];     // per-chunk source edge index
__device__ unsigned int   g_acnt[NCMAX];
__device__ unsigned int   g_abase[NCMAX];
__device__ unsigned int g_rec[MACC];          // accepted i -> (win_min<<16)|lose_min
__device__ unsigned int g_ev2[EVN];           // event keys (v<<16)|k, then sorted
__device__ unsigned int g_parent[NN];
__device__ float        g_alt[NN];
__device__ unsigned int g_chw[MACC];          // child node on win-min side
__device__ unsigned int g_chl[MACC];          // child node on lose-min side
__device__ unsigned long long g_nd[2][ELEN + 1];  // Euler (nx | dd<<32), ping-pong
__device__ unsigned int g_pos[ELEN];          // Euler position
__device__ float        g_ev[20 * EP];        // planes 0..9 leaf moments, 10..19 path sums
__device__ float        g_part[20 * 256];     // scan block partials

// ---------------- init (fused zeroing) ----------------
__global__ void k_init(int M) {
    int i = blockIdx.x * blockDim.x + threadIdx.x;   // 262144 threads
    if (i < NN) { g_parent[i] = i; g_alt[i] = 0.0f; }
    if (i < NB) g_bcnt[i] = 0u;
    if (i >= 2 * MACC && i < EVN) g_ev2[i] = FULLM;
    #pragma unroll
    for (int p = 0; p < 10; p++) g_ev[p * EP + i] = 0.0f;   // planes 0..9 fully
    if (i >= ELEN) {                                        // planes 10..19: tail only
        #pragma unroll
        for (int p = 10; p < 20; p++) g_ev[p * EP + i] = 0.0f;
    }
}

// ---------------- bucket sort of (weight, idx) keys ----------------
__global__ void k_bscatter(const float* __restrict__ ew, int M) {
    int e = blockIdx.x * blockDim.x + threadIdx.x;
    if (e >= M) return;
    float w = ew[e];
    unsigned int b = min((unsigned int)(w * (float)NB), (unsigned int)(NB - 1));
    unsigned int slot = atomicAdd(&g_bcnt[b], 1u);
    if (slot < BCAP)
        g_keys2[b * BCAP + slot] = ((unsigned long long)__float_as_uint(w) << 32) | (unsigned int)e;
}

__global__ void k_bscan() {
    __shared__ unsigned int s[1024];
    __shared__ unsigned int s_run;
    int t = threadIdx.x;
    if (t == 0) s_run = 0u;
    __syncthreads();
    for (int c = 0; c < NB / 1024; c++) {
        unsigned int x = g_bcnt[c * 1024 + t];
        s[t] = x;
        __syncthreads();
        for (int off = 1; off < 1024; off <<= 1) {
            unsigned int y = (t >= off) ? s[t - off] : 0u;
            __syncthreads();
            s[t] += y;
            __syncthreads();
        }
        unsigned int run = s_run;
        g_boffs[c * 1024 + t] = run + s[t] - x;   // exclusive
        unsigned int tot = s[1023];
        __syncthreads();
        if (t == 0) s_run = run + tot;
        __syncthreads();
    }
}

// warp-per-bucket 64-wide bitonic (unique keys => stability); compacts + gathers endpoints
__global__ void __launch_bounds__(256) k_bsort(const int* __restrict__ src,
                                               const int* __restrict__ dst) {
    __shared__ unsigned long long s[8][BCAP];
    int wid  = threadIdx.x >> 5;
    int lane = threadIdx.x & 31;
    int b = blockIdx.x * 8 + wid;
    unsigned int cnt  = min(g_bcnt[b], (unsigned int)BCAP);
    unsigned int offs = g_boffs[b];
    s[wid][lane]      = (lane < (int)cnt)      ? g_keys2[b * BCAP + lane]      : ~0ull;
    s[wid][lane + 32] = (lane + 32 < (int)cnt) ? g_keys2[b * BCAP + lane + 32] : ~0ull;
    __syncwarp();
    #pragma unroll
    for (int k = 2; k <= BCAP; k <<= 1) {
        for (int j = k >> 1; j > 0; j >>= 1) {
            int pos = ((lane & ~(j - 1)) << 1) | (lane & (j - 1));
            bool asc = ((pos & k) == 0);
            unsigned long long x = s[wid][pos], y = s[wid][pos + j];
            if ((x > y) == asc) { s[wid][pos] = y; s[wid][pos + j] = x; }
            __syncwarp();
        }
    }
    for (int i = lane; i < (int)cnt; i += 32) {
        unsigned long long key = s[wid][i];
        unsigned int idx = (unsigned int)(key & 0xFFFFFFFFull);
        unsigned int wb  = (unsigned int)(key >> 32);
        unsigned int u = (unsigned int)src[idx];
        unsigned int v = (unsigned int)dst[idx];
        g_esort[offs + i] = ((unsigned long long)wb << 32) | (v << 16) | u;
    }
}

// ---------------- phase 1: chunk-boundary labels, UF in shared memory ----------------
__device__ __forceinline__ unsigned int sfind(volatile unsigned short* uf, unsigned int x) {
    unsigned int p;
    while ((p = uf[x]) != x) {
        unsigned int gp = uf[p];
        if (gp != p) uf[x] = (unsigned short)gp;   // path halving (benign races)
        x = p;
    }
    return x;
}

__global__ void __launch_bounds__(1024) k_phase1(int M, int nc) {
    extern __shared__ unsigned short s_uf[];   // 65536 x u16 = 128KB
    int t = threadIdx.x;
    unsigned int* uf32 = (unsigned int*)s_uf;
    for (int i = t; i < L_ / 2; i += 1024)
        uf32[i] = (2u * i) | ((2u * i + 1u) << 16);
    __syncthreads();
    for (int c = 0; c < nc; c++) {
        int base = c * CHUNK;
        int n = min(CHUNK, M - base);
        for (int e = t; e < n; e += 1024) {
            unsigned long long cur = g_esort[base + e];
            unsigned int u = (unsigned int)cur & 0xFFFFu;
            unsigned int v = ((unsigned int)cur >> 16) & 0xFFFFu;
            unsigned int a = sfind(s_uf, u);
            unsigned int b = sfind(s_uf, v);
            g_lab[base + e] = a | (b << 16);
        }
        __syncthreads();
        for (int e = t; e < n; e += 1024) {
            unsigned long long cur = g_esort[base + e];
            unsigned int u = (unsigned int)cur & 0xFFFFu;
            unsigned int v = ((unsigned int)cur >> 16) & 0xFFFFu;
            for (;;) {
                unsigned int a = sfind(s_uf, u), b = sfind(s_uf, v);
                if (a == b) break;
                unsigned int hi = a > b ? a : b;
                unsigned int lo = a ^ b ^ hi;
                if (atomicCAS((unsigned short*)&s_uf[hi], (unsigned short)hi,
                              (unsigned short)lo) == (unsigned short)hi) break;
            }
        }
        __syncthreads();
    }
}

// ---------------- phase 2: independent serial replay per chunk ----------------
__device__ __forceinline__ unsigned int uf_find(volatile unsigned short* uf, unsigned int x) {
    unsigned int r = x, p;
    while ((p = uf[r]) != r) r = p;
    while ((p = uf[x]) != r) { uf[x] = (unsigned short)r; x = p; }
    return r;
}

__global__ void __launch_bounds__(1024) k_phase2(int M) {
    extern __shared__ unsigned short s_uf[];
    int c = blockIdx.x;
    int base = c * CHUNK;
    int n = min(CHUNK, M - base);
    unsigned int* uf32 = (unsigned int*)s_uf;
    for (int i = threadIdx.x; i < L_ / 2; i += blockDim.x)
        uf32[i] = (2u * i) | ((2u * i + 1u) << 16);
    __syncthreads();
    if (threadIdx.x == 0) {
        unsigned int cnt = 0;
        for (int e = 0; e < n; e++) {
            unsigned int lab = g_lab[base + e];
            unsigned int a = uf_find(s_uf, lab & 0xFFFFu);
            unsigned int b = uf_find(s_uf, lab >> 16);
            if (a == b) continue;
            unsigned int w = a < b ? a : b;
            unsigned int l = a ^ b ^ w;
            s_uf[l] = (unsigned short)w;
            g_recTmp[base + cnt] = (w << 16) | l;
            g_srcTmp[base + cnt] = (unsigned int)(base + e);
            cnt++;
        }
        g_acnt[c] = cnt;
    }
}

__global__ void k_ascan(int nc) {
    __shared__ unsigned int s[NCMAX];
    int t = threadIdx.x;
    unsigned int x = (t < nc) ? g_acnt[t] : 0u;
    s[t] = x;
    __syncthreads();
    for (int off = 1; off < NCMAX; off <<= 1) {
        unsigned int y = (t >= off) ? s[t - off] : 0u;
        __syncthreads();
        s[t] += y;
        __syncthreads();
    }
    if (t < nc) g_abase[t] = s[t] - x;   // exclusive
}

__global__ void k_ascatter(int nc) {
    int i = blockIdx.x * blockDim.x + threadIdx.x;
    int c = i / CHUNK, li = i % CHUNK;
    if (c >= nc || (unsigned int)li >= g_acnt[c]) return;
    unsigned int slot = g_abase[c] + (unsigned int)li;
    unsigned int rec = g_recTmp[c * CHUNK + li];
    g_rec[slot] = rec;
    unsigned int e = g_srcTmp[c * CHUNK + li];
    g_alt[L_ + slot] = __uint_as_float((unsigned int)(g_esort[e] >> 32));
    g_ev2[2 * slot]     = ((rec >> 16) << 16) | slot;       // win event
    g_ev2[2 * slot + 1] = ((rec & 0xFFFFu) << 16) | slot;   // lose event
}

// ---------------- bitonic sort, 32-bit event keys (8192-wide tiles) ----------------
__global__ void __launch_bounds__(1024) k_esort_local_init() {
    __shared__ unsigned int s[8192];
    int base = blockIdx.x * 8192;
    int t = threadIdx.x;
    #pragma unroll
    for (int i = 0; i < 8; i++) s[t + i * 1024] = g_ev2[base + t + i * 1024];
    __syncthreads();
    for (int k = 2; k <= 8192; k <<= 1) {
        for (int j = k >> 1; j > 0; j >>= 1) {
            #pragma unroll
            for (int q = 0; q < 4; q++) {
                int p = t + q * 1024;
                int pos = ((p & ~(j - 1)) << 1) | (p & (j - 1));
                bool asc = (((base + pos) & k) == 0);
                unsigned int x = s[pos], y = s[pos + j];
                if ((x > y) == asc) { s[pos] = y; s[pos + j] = x; }
            }
            __syncthreads();
        }
    }
    #pragma unroll
    for (int i = 0; i < 8; i++) g_ev2[base + t + i * 1024] = s[t + i * 1024];
}

__global__ void k_esort_global(int j, int k) {
    int t = blockIdx.x * blockDim.x + threadIdx.x;
    int i = ((t & ~(j - 1)) << 1) | (t & (j - 1));
    int l = i + j;
    bool asc = ((i & k) == 0);
    unsigned int x = g_ev2[i], y = g_ev2[l];
    if ((x > y) == asc) { g_ev2[i] = y; g_ev2[l] = x; }
}

__global__ void __launch_bounds__(1024) k_esort_local_tail(int k) {
    __shared__ unsigned int s[8192];
    int base = blockIdx.x * 8192;
    int t = threadIdx.x;
    #pragma unroll
    for (int i = 0; i < 8; i++) s[t + i * 1024] = g_ev2[base + t + i * 1024];
    __syncthreads();
    bool asc = ((base & k) == 0);   // k >= 16384 > tile: constant per tile
    for (int j = 4096; j > 0; j >>= 1) {
        #pragma unroll
        for (int q = 0; q < 4; q++) {
            int p = t + q * 1024;
            int pos = ((p & ~(j - 1)) << 1) | (p & (j - 1));
            unsigned int x = s[pos], y = s[pos + j];
            if ((x > y) == asc) { s[pos] = y; s[pos + j] = x; }
        }
        __syncthreads();
    }
    #pragma unroll
    for (int i = 0; i < 8; i++) g_ev2[base + t + i * 1024] = s[t + i * 1024];
}

// parallel chain links from sorted events
__global__ void k_vlink2() {
    int i = blockIdx.x * blockDim.x + threadIdx.x;
    if (i >= 2 * MACC) return;
    unsigned int key = g_ev2[i];
    unsigned int v = key >> 16, k = key & 0xFFFFu;
    unsigned int prevnode;
    if (i == 0 || (g_ev2[i - 1] >> 16) != v)
        prevnode = v;
    else
        prevnode = L_ + (g_ev2[i - 1] & 0xFFFFu);
    g_parent[prevnode] = L_ + k;
    if ((g_rec[k] >> 16) == v) g_chw[k] = prevnode;
    else                       g_chl[k] = prevnode;
}

// ---------------- Euler tour + list ranking (quad-hop doubling) ----------------
__global__ void k_euler() {
    int n = blockIdx.x * blockDim.x + threadIdx.x;
    if (n >= NN) return;
    if (n == 0) g_nd[0][ESENT] = (unsigned long long)ESENT;   // dd=0 self-loop
    const unsigned long long ONE = 1ull << 32;
    if (n < L_) {
        g_nd[0][n] = (unsigned long long)(NN + n) | ONE;
    } else {
        int k = n - L_;
        unsigned int cw = g_chw[k], cl = g_chl[k];
        g_nd[0][n]       = (unsigned long long)cw | ONE;
        g_nd[0][NN + cw] = (unsigned long long)cl | ONE;
        g_nd[0][NN + cl] = (unsigned long long)(NN + n) | ONE;
    }
    if (n == NN - 1) g_nd[0][NN + n] = (unsigned long long)ESENT | ONE;
}

// quad-hop: one launch = two doubling rounds (4 hops). 4^9 = 2^18 >= ELEN+1 list length.
__global__ void k_rank4(int s) {
    int e = blockIdx.x * blockDim.x + threadIdx.x;
    if (e > ELEN) return;
    unsigned long long a = g_nd[s][e];
    unsigned long long b = g_nd[s][(unsigned int)a];
    unsigned long long c = g_nd[s][(unsigned int)b];
    unsigned long long d = g_nd[s][(unsigned int)c];
    unsigned long long dd = (a >> 32) + (b >> 32) + (c >> 32) + (d >> 32);
    g_nd[1 - s][e] = (unsigned long long)(unsigned int)d | (dd << 32);
}

// final: positions; fuse leaf moment scatter (element id < L_ = down(leaf))
__global__ void k_rank_fin(int s) {
    int e = blockIdx.x * blockDim.x + threadIdx.x;
    if (e >= ELEN) return;
    unsigned long long x = g_nd[s][e];
    unsigned long long y = g_nd[s][(unsigned int)x];
    unsigned int dd = (unsigned int)((x >> 32) + (y >> 32));
    unsigned int p = (unsigned int)ELEN - dd;
    g_pos[e] = p;
    if (e < L_) {   // down(leaf e): scatter moments of alt(parent(leaf))
        float yv = g_alt[g_parent[e]];
        float pw = 1.0f;
        #pragma unroll
        for (int i = 0; i < 10; i++) { g_ev[i * EP + p] = pw; pw *= yv; }
    }
}

// planes 10..19: +val at down(n), -val at up(n); sz from Euler positions:
// leaves(n) = (pos_up - pos_down + 3) >> 2  (full binary tree)
__global__ void k_pscatter() {
    int n = blockIdx.x * blockDim.x + threadIdx.x;
    if (n >= NN) return;
    unsigned int pd = g_pos[n], pu = g_pos[NN + n];
    float sz = (float)((pu - pd + 3u) >> 2);
    float x  = g_alt[n];
    unsigned int p = g_parent[n];
    bool isroot = (p == (unsigned int)n);
    float y = g_alt[p];
    float xp = 1.0f, yp = 1.0f;
    #pragma unroll
    for (int i = 0; i < 10; i++) {
        float val = sz * (xp - (isroot ? 0.0f : yp));
        g_ev[(10 + i) * EP + pd] = val;
        g_ev[(10 + i) * EP + pu] = -val;
        xp *= x; yp *= y;
    }
}

// ---------------- shuffle-based 3-phase inclusive prefix scan (20 planes) ----------
__global__ void k_scan1() {
    __shared__ float warp_sums[32];
    int plane = blockIdx.y;
    int gi = blockIdx.x * 1024 + threadIdx.x;
    int t = threadIdx.x;
    int lane = t & 31, wid = t >> 5;
    float x = g_ev[plane * EP + gi];
    // warp-level inclusive scan
    #pragma unroll
    for (int off = 1; off < 32; off <<= 1) {
        float y = __shfl_up_sync(FULLM, x, off);
        if (lane >= off) x += y;
    }
    if (lane == 31) warp_sums[wid] = x;
    __syncthreads();
    if (wid == 0) {
        float w = warp_sums[lane];
        #pragma unroll
        for (int off = 1; off < 32; off <<= 1) {
            float y = __shfl_up_sync(FULLM, w, off);
            if (lane >= off) w += y;
        }
        warp_sums[lane] = w;
    }
    __syncthreads();
    float blk = (wid > 0) ? warp_sums[wid - 1] : 0.0f;
    float res = x + blk;
    g_ev[plane * EP + gi] = res;
    if (t == 1023) g_part[plane * 256 + blockIdx.x] = res;
}

__global__ void k_scan2() {
    __shared__ float warp_sums[8];
    int plane = blockIdx.y;
    int t = threadIdx.x;   // 256 threads
    int lane = t & 31, wid = t >> 5;
    float x = g_part[plane * 256 + t];
    float orig = x;
    #pragma unroll
    for (int off = 1; off < 32; off <<= 1) {
        float y = __shfl_up_sync(FULLM, x, off);
        if (lane >= off) x += y;
    }
    if (lane == 31) warp_sums[wid] = x;
    __syncthreads();
    if (wid == 0 && lane < 8) {
        float w = warp_sums[lane];
        #pragma unroll
        for (int off = 1; off < 8; off <<= 1) {
            float y = __shfl_up_sync(0xFFu, w, off);
            if (lane >= off) w += y;
        }
        warp_sums[lane] = w;
    }
    __syncthreads();
    float blk = (wid > 0) ? warp_sums[wid - 1] : 0.0f;
    g_part[plane * 256 + t] = x + blk - orig;   // exclusive
}

__global__ void k_scan3() {
    int plane = blockIdx.y;
    int gi = blockIdx.x * 1024 + threadIdx.x;
    g_ev[plane * EP + gi] += g_part[plane * 256 + blockIdx.x];
}

// ---------------- sigmoid via degree-9 Taylor, binomial moment combine ----------------
__device__ __forceinline__ float sig_combine(float x, const float* A) {
    float xp[10];
    xp[0] = 1.0f;
    #pragma unroll
    for (int p = 1; p < 10; p++) xp[p] = xp[p - 1] * x;
    float B0 = A[0];
    float B1 = xp[1] * A[0] - A[1];
    float B3 = xp[3] * A[0] - 3.0f * xp[2] * A[1] + 3.0f * xp[1] * A[2] - A[3];
    float B5 = xp[5] * A[0] - 5.0f * xp[4] * A[1] + 10.0f * xp[3] * A[2]
             - 10.0f * xp[2] * A[3] + 5.0f * xp[1] * A[4] - A[5];
    float B7 = xp[7] * A[0] - 7.0f * xp[6] * A[1] + 21.0f * xp[5] * A[2]
             - 35.0f * xp[4] * A[3] + 35.0f * xp[3] * A[4] - 21.0f * xp[2] * A[5]
             + 7.0f * xp[1] * A[6] - A[7];
    float B9 = xp[9] * A[0] - 9.0f * xp[8] * A[1] + 36.0f * xp[7] * A[2]
             - 84.0f * xp[6] * A[3] + 126.0f * xp[5] * A[4] - 126.0f * xp[4] * A[5]
             + 84.0f * xp[3] * A[6] - 36.0f * xp[2] * A[7] + 9.0f * xp[1] * A[8] - A[9];
    return 0.5f * B0 + 0.25f * B1 - 0.0208333333f * B3 + 0.0020833333f * B5
         - 2.1081349e-4f * B7 + 2.1357107e-5f * B9;
}

// ---------------- final: out = outside + (leaf ? 0.5 : inside), fused ----------------
__global__ void k_final(float* __restrict__ out) {
    int n = blockIdx.x * blockDim.x + threadIdx.x;
    if (n >= NN) return;
    unsigned int pd = g_pos[n], pu = g_pos[NN + n];
    float sz = (float)((pu - pd + 3u) >> 2);
    float x  = g_alt[n];
    float A[10];
    float xp = 1.0f;
    #pragma unroll
    for (int i = 0; i < 10; i++) {
        A[i] = g_ev[(10 + i) * EP + pd] - sz * xp;   // strict ancestors only
        xp *= x;
    }
    float outside = sig_combine(x, A);
    float self;
    if (n < L_) {
        self = 0.5f;
    } else {   // inside from subtree moments (planes 0..9)
        float T[10];
        #pragma unroll
        for (int i = 0; i < 10; i++) T[i] = g_ev[i * EP + pu] - g_ev[i * EP + pd];
        self = sig_combine(x, T);
    }
    out[n] = outside + self;
}

// ---------------- launch ----------------
extern "C" void kernel_launch(void* const* d_in, const int* in_sizes, int n_in,
                              void* d_out, int out_size) {
    const float* ew  = (const float*)d_in[0];
    const int*   src = (const int*)d_in[1];
    const int*   dst = (const int*)d_in[2];
    int M = in_sizes[0];   // 130560
    int nc = (M + CHUNK - 1) / CHUNK;   // 128

    k_init<<<NPAD / 256, 256>>>(M);

    // bucket sort (padded scatter -> scan -> warp-per-bucket sort + compact)
    k_bscatter<<<(M + 255) / 256, 256>>>(ew, M);
    k_bscan<<<1, 1024>>>();
    k_bsort<<<NB / 8, 256>>>(src, dst);

    // tree build (round-12 proven path)
    cudaFuncSetAttribute(k_phase1, cudaFuncAttributeMaxDynamicSharedMemorySize, L_ * 2);
    cudaFuncSetAttribute(k_phase2, cudaFuncAttributeMaxDynamicSharedMemorySize, L_ * 2);
    k_phase1<<<1, 1024, L_ * 2>>>(M, nc);
    k_phase2<<<nc, 1024, L_ * 2>>>(M);
    k_ascan<<<1, NCMAX>>>(nc);
    k_ascatter<<<(nc * CHUNK + 255) / 256, 256>>>(nc);

    // event sort (8192-wide tiles, round-12 proven) + chain links
    k_esort_local_init<<<EVN / 8192, 1024>>>();
    for (int k = 16384; k <= EVN; k <<= 1) {
        for (int j = k >> 1; j >= 8192; j >>= 1)
            k_esort_global<<<(EVN / 2) / 256, 256>>>(j, k);
        k_esort_local_tail<<<EVN / 8192, 1024>>>(k);
    }
    k_vlink2<<<(2 * MACC + 255) / 256, 256>>>();

    // Euler tour + quad-hop list ranking (9 rounds) + fused final
    k_euler<<<(NN + 255) / 256, 256>>>();
    int s = 0;
    for (int r = 0; r < 9; r++) {
        k_rank4<<<(ELEN + 1 + 255) / 256, 256>>>(s);
        s = 1 - s;
    }
    k_rank_fin<<<(ELEN + 255) / 256, 256>>>(s);

    // path-sum scatter (sizes from Euler positions)
    k_pscatter<<<(NN + 255) / 256, 256>>>();

    // single scan round over all 20 planes (shuffle-based)
    {
        dim3 g1(256, 20); k_scan1<<<g1, 1024>>>();
        dim3 g2(1, 20);   k_scan2<<<g2, 256>>>();
        dim3 g3(256, 20); k_scan3<<<g3, 1024>>>();
    }

    k_final<<<(NN + 255) / 256, 256>>>((float*)d_out);
}